// round 12
// baseline (speedup 1.0000x reference)
#include <cuda_runtime.h>
#include <cuda_fp16.h>
#include <math.h>
#include <stdint.h>

// Problem dims
#define Bn 2
#define Tn 1024
#define Cn 1024
#define Hn 16
#define Dn 64
#define BTn (Bn * Tn)
#define NTOK (Bn * Tn * Cn)
#define W_LR 64
#define A_LR 64
#define V_LR 64
#define G_LR 160
#define DECAY_SCALE (-0.6065306597126334f)
#define GN_EPS (64.0f * 1e-5f)
#define SS 8

// fp16 weight scratch offsets (in elements)
#define OFF_Wr 0
#define OFF_Wk 1048576
#define OFF_Wv 2097152
#define OFF_Wo 3145728
#define OFF_wA 4194304
#define OFF_aA 4259840
#define OFF_vA 4325376
#define OFF_gA 4390912
#define OFF_wB 4554752
#define OFF_aB 4620288
#define OFF_vB 4685824
#define OFF_gB 4751360
#define WTS_TOTAL 4915200

// ---------------- scratch (__device__ globals) -----------------------------
__device__ __align__(16) __half g_xr[NTOK], g_xw[NTOK], g_xk[NTOK], g_xv[NTOK], g_xa[NTOK], g_xg[NTOK];
__device__ float g_r[NTOK], g_k0[NTOK], g_v[NTOK], g_w[NTOK], g_a[NTOK], g_g[NTOK];
__device__ float g_kf[NTOK];
__device__ float g_m[NTOK], g_ad[NTOK], g_rd[NTOK], g_bb[NTOK];
__device__ float g_rb[BTn * Hn], g_rk[BTn * Hn];
__device__ float g_osc[NTOK];
__device__ __align__(16) __half g_y[NTOK];
__device__ __align__(16) __half g_tmpW[BTn * W_LR], g_tmpA[BTn * A_LR], g_tmpV[BTn * V_LR], g_tmpG[BTn * G_LR];
__device__ __align__(16) __half g_wts[WTS_TOTAL];

// ---------------- helpers --------------------------------------------------
__device__ __forceinline__ float sigmoidf_(float x) { return 1.f / (1.f + expf(-x)); }

__device__ __forceinline__ void cpasync16(void* smem, const void* gptr, int srcbytes) {
    uint32_t s = (uint32_t)__cvta_generic_to_shared(smem);
    asm volatile("cp.async.ca.shared.global [%0], [%1], 16, %2;" :: "r"(s), "l"(gptr), "r"(srcbytes));
}
__device__ __forceinline__ void cpasync4(void* smem, const void* gptr) {
    uint32_t s = (uint32_t)__cvta_generic_to_shared(smem);
    asm volatile("cp.async.ca.shared.global [%0], [%1], 4;" :: "r"(s), "l"(gptr));
}
__device__ __forceinline__ void cpcommit() { asm volatile("cp.async.commit_group;"); }
__device__ __forceinline__ void cpwait2() { asm volatile("cp.async.wait_group 2;"); }
__device__ __forceinline__ void cpwait1() { asm volatile("cp.async.wait_group 1;"); }
__device__ __forceinline__ void cpwait0() { asm volatile("cp.async.wait_group 0;"); }

__device__ __forceinline__ float2 ffma2(float2 a, float2 b, float2 c) {
    unsigned long long ua = *(unsigned long long*)&a;
    unsigned long long ub = *(unsigned long long*)&b;
    unsigned long long uc = *(unsigned long long*)&c;
    unsigned long long ud;
    asm("fma.rn.f32x2 %0, %1, %2, %3;" : "=l"(ud) : "l"(ua), "l"(ub), "l"(uc));
    return *(float2*)&ud;
}
__device__ __forceinline__ float2 fmul2(float2 a, float2 b) {
    unsigned long long ua = *(unsigned long long*)&a;
    unsigned long long ub = *(unsigned long long*)&b;
    unsigned long long ud;
    asm("mul.rn.f32x2 %0, %1, %2;" : "=l"(ud) : "l"(ua), "l"(ub));
    return *(float2*)&ud;
}

__device__ __forceinline__ void mma_f16(float* d, const uint32_t* a, const uint32_t* b) {
    asm volatile(
        "mma.sync.aligned.m16n8k16.row.col.f32.f16.f16.f32 "
        "{%0,%1,%2,%3}, {%4,%5,%6,%7}, {%8,%9}, {%0,%1,%2,%3};"
        : "+f"(d[0]), "+f"(d[1]), "+f"(d[2]), "+f"(d[3])
        : "r"(a[0]), "r"(a[1]), "r"(a[2]), "r"(a[3]), "r"(b[0]), "r"(b[1]));
}

// ---------------- mix + weight fp16 conversion, vectorized -----------------
__device__ __forceinline__ uint2 mix4h(float4 h, float4 d, const float* mxp) {
    float4 mx = *(const float4*)mxp;
    __half2 lo = __floats2half2_rn(fmaf(d.x, mx.x, h.x), fmaf(d.y, mx.y, h.y));
    __half2 hi = __floats2half2_rn(fmaf(d.z, mx.z, h.z), fmaf(d.w, mx.w, h.w));
    uint2 r;
    r.x = *(uint32_t*)&lo; r.y = *(uint32_t*)&hi;
    return r;
}

__global__ void mixcvt_kernel(const float* __restrict__ hs, const float* __restrict__ xmix,
                              const float* __restrict__ Wr, const float* __restrict__ Wk,
                              const float* __restrict__ Wv, const float* __restrict__ Wo,
                              const float* __restrict__ wA, const float* __restrict__ aA,
                              const float* __restrict__ vA, const float* __restrict__ gA,
                              const float* __restrict__ wB, const float* __restrict__ aB,
                              const float* __restrict__ vB, const float* __restrict__ gB) {
    int i4 = blockIdx.x * blockDim.x + threadIdx.x;
    const int NTOK4 = NTOK / 4;
    if (i4 < NTOK4) {
        int base = i4 * 4;
        int c = base & (Cn - 1);
        int t = (base / Cn) & (Tn - 1);
        float4 h = *(const float4*)(hs + base);
        float4 p = (t == 0) ? make_float4(0.f, 0.f, 0.f, 0.f)
                            : *(const float4*)(hs + base - Cn);
        float4 d = make_float4(p.x - h.x, p.y - h.y, p.z - h.z, p.w - h.w);
        *(uint2*)(g_xr + base) = mix4h(h, d, xmix + 0 * Cn + c);
        *(uint2*)(g_xw + base) = mix4h(h, d, xmix + 1 * Cn + c);
        *(uint2*)(g_xk + base) = mix4h(h, d, xmix + 2 * Cn + c);
        *(uint2*)(g_xv + base) = mix4h(h, d, xmix + 3 * Cn + c);
        *(uint2*)(g_xa + base) = mix4h(h, d, xmix + 4 * Cn + c);
        *(uint2*)(g_xg + base) = mix4h(h, d, xmix + 5 * Cn + c);
    } else {
        int j = (i4 - NTOK4) * 4;
        if (j >= WTS_TOTAL) return;
        const float* src;
        if (j < OFF_Wk)      src = Wr + (j - OFF_Wr);
        else if (j < OFF_Wv) src = Wk + (j - OFF_Wk);
        else if (j < OFF_Wo) src = Wv + (j - OFF_Wv);
        else if (j < OFF_wA) src = Wo + (j - OFF_Wo);
        else if (j < OFF_aA) src = wA + (j - OFF_wA);
        else if (j < OFF_vA) src = aA + (j - OFF_aA);
        else if (j < OFF_gA) src = vA + (j - OFF_vA);
        else if (j < OFF_wB) src = gA + (j - OFF_gA);
        else if (j < OFF_aB) src = wB + (j - OFF_wB);
        else if (j < OFF_vB) src = aB + (j - OFF_aB);
        else if (j < OFF_gB) src = vB + (j - OFF_vB);
        else                 src = gB + (j - OFF_gB);
        float4 v = *(const float4*)src;
        __half2 lo = __floats2half2_rn(v.x, v.y);
        __half2 hi = __floats2half2_rn(v.z, v.w);
        uint2 r; r.x = *(uint32_t*)&lo; r.y = *(uint32_t*)&hi;
        *(uint2*)(g_wts + j) = r;
    }
}

// ---------------- tensor-core fp16 GEMM, BM=128 BN=64 BK=32, 3-stage -------
// 8 warps as 4(M) x 2(N): WM=32 (MF=2), WN=32. acc = 32 regs/thread.
// epi: 0 plain fp32, 1 tanh->half, 2 sigmoid->half, 3 sigmoid(x+bias) fp32,
//      4 DECAY*sigmoid(x+bias) fp32, 5 lerp fp32, 6 plain->half
struct Job {
    const __half* A; const __half* W; void* O;
    const float* bias; const float* p1; const float* p2;
    int epi; int N; int K;
};
struct Jobs { Job j[4]; };

#define LDPh 40   // halves per smem row
#define BNt 64
#define MF 2
#define PIPE 3

__global__ __launch_bounds__(256, 3) void gemmTC(Jobs jobs) {
    extern __shared__ __half hsm[];
    // layout: PIPE buffers, each [128+64][LDPh]
    __half* As = hsm;                           // [PIPE][128][LDPh]
    __half* Bs = hsm + PIPE * 128 * LDPh;       // [PIPE][64][LDPh]

    Job jb = jobs.j[blockIdx.z];
    const int N = jb.N, K = jb.K;
    const int row0 = blockIdx.y * 128;
    const int col0 = blockIdx.x * BNt;
    if (col0 >= N) return;
    const int tid = threadIdx.x;
    const int wid = tid >> 5, lane = tid & 31;
    const int wm = wid & 3, wn = wid >> 2;     // 4 x 2
    const int mbase = wm * 32, nbase = wn * 32;
    const int g = lane >> 2, q = lane & 3;

    const int arow = tid >> 1;
    const int ah0 = (tid & 1) * 16;

    auto stageTiles = [&](int kt, int b) {
        const __half* Ap = jb.A + (size_t)(row0 + arow) * K + kt * 32 + ah0;
        __half* Ad = &As[(b * 128 + arow) * LDPh + ah0];
        cpasync16(Ad + 0, Ap + 0, 16);
        cpasync16(Ad + 8, Ap + 8, 16);
        int brow = tid >> 2, bh0 = (tid & 3) * 8;
        int bn0 = col0 + brow;
        const __half* Bp = jb.W + (size_t)bn0 * K + kt * 32 + bh0;
        cpasync16(&Bs[(b * BNt + brow) * LDPh + bh0], Bp, (bn0 < N) ? 16 : 0);
        cpcommit();
    };

    float acc[MF][4][4];
#pragma unroll
    for (int i = 0; i < MF; i++)
#pragma unroll
        for (int j2 = 0; j2 < 4; j2++)
#pragma unroll
            for (int k2 = 0; k2 < 4; k2++) acc[i][j2][k2] = 0.f;

    const int nk = K >> 5;

    stageTiles(0, 0);
    if (nk > 1) stageTiles(1, 1);

    int buf = 0;
    for (int kt = 0; kt < nk; kt++) {
        if (kt + 2 < nk) {
            int nb = buf + 2; if (nb >= PIPE) nb -= PIPE;
            stageTiles(kt + 2, nb);
            cpwait2();
        } else if (kt + 1 < nk) {
            cpwait1();
        } else {
            cpwait0();
        }
        __syncthreads();

        const uint32_t* Au = (const uint32_t*)(As + buf * 128 * LDPh);
        const uint32_t* Bu = (const uint32_t*)(Bs + buf * BNt * LDPh);
#pragma unroll
        for (int kw = 0; kw < 16; kw += 8) {
            uint32_t af[MF][4], bf[4][2];
#pragma unroll
            for (int mf = 0; mf < MF; mf++) {
                int m = mbase + mf * 16 + g;
                af[mf][0] = Au[m * (LDPh / 2) + kw + q];
                af[mf][1] = Au[(m + 8) * (LDPh / 2) + kw + q];
                af[mf][2] = Au[m * (LDPh / 2) + kw + q + 4];
                af[mf][3] = Au[(m + 8) * (LDPh / 2) + kw + q + 4];
            }
#pragma unroll
            for (int nf = 0; nf < 4; nf++) {
                int n = nbase + nf * 8 + g;
                bf[nf][0] = Bu[n * (LDPh / 2) + kw + q];
                bf[nf][1] = Bu[n * (LDPh / 2) + kw + q + 4];
            }
#pragma unroll
            for (int mf = 0; mf < MF; mf++)
#pragma unroll
                for (int nf = 0; nf < 4; nf++) mma_f16(acc[mf][nf], af[mf], bf[nf]);
        }
        __syncthreads();
        buf++; if (buf >= PIPE) buf = 0;
    }

    const int epi = jb.epi;
#pragma unroll
    for (int mf = 0; mf < MF; mf++) {
#pragma unroll
        for (int nf = 0; nf < 4; nf++) {
            int r0 = row0 + mbase + mf * 16 + g;
            int c = col0 + nbase + nf * 8 + 2 * q;
            if (c >= N) continue;
#pragma unroll
            for (int rr = 0; rr < 2; rr++) {
                int r = r0 + rr * 8;
                float x0 = acc[mf][nf][rr * 2 + 0];
                float x1 = acc[mf][nf][rr * 2 + 1];
                if (epi == 0) {
                    *(float2*)((float*)jb.O + (size_t)r * N + c) = make_float2(x0, x1);
                } else if (epi == 6) {
                    __half2 hv = __floats2half2_rn(x0, x1);
                    *(__half2*)((__half*)jb.O + (size_t)r * N + c) = hv;
                } else if (epi == 1) {
                    __half2 hv = __floats2half2_rn(tanhf(x0), tanhf(x1));
                    *(__half2*)((__half*)jb.O + (size_t)r * N + c) = hv;
                } else if (epi == 2) {
                    __half2 hv = __floats2half2_rn(sigmoidf_(x0), sigmoidf_(x1));
                    *(__half2*)((__half*)jb.O + (size_t)r * N + c) = hv;
                } else if (epi == 3) {
                    float y0 = sigmoidf_(x0 + __ldg(jb.bias + c));
                    float y1 = sigmoidf_(x1 + __ldg(jb.bias + c + 1));
                    *(float2*)((float*)jb.O + (size_t)r * N + c) = make_float2(y0, y1);
                } else if (epi == 4) {
                    float y0 = DECAY_SCALE * sigmoidf_(x0 + __ldg(jb.bias + c));
                    float y1 = DECAY_SCALE * sigmoidf_(x1 + __ldg(jb.bias + c + 1));
                    *(float2*)((float*)jb.O + (size_t)r * N + c) = make_float2(y0, y1);
                } else { // 5
                    size_t i0 = (size_t)r * N + c;
                    float s0 = sigmoidf_(x0 + __ldg(jb.bias + c));
                    float s1 = sigmoidf_(x1 + __ldg(jb.bias + c + 1));
                    float a0 = jb.p1[i0], b0 = jb.p2[i0];
                    float a1 = jb.p1[i0 + 1], b1 = jb.p2[i0 + 1];
                    float y0 = fmaf(s0, b0 - a0, a0);
                    float y1 = fmaf(s1, b1 - a1, a1);
                    *(float2*)((float*)jb.O + i0) = make_float2(y0, y1);
                }
            }
        }
    }
}

// ---------------- prep: kk-normalize, k-final, scan precomputes ------------
__global__ void prep_kernel(const float* __restrict__ k_k, const float* __restrict__ k_a) {
    int gid = blockIdx.x * (blockDim.x >> 5) + (threadIdx.x >> 5);
    int lane = threadIdx.x & 31;
    if (gid >= BTn * Hn) return;
    int bt = gid >> 4, h = gid & 15;
    size_t base = (size_t)bt * Cn + h * Dn;
    int c0 = h * Dn + lane, c1 = c0 + 32;

    float k0a = g_k0[base + lane], k0b = g_k0[base + lane + 32];
    float q0 = k0a * k_k[c0], q1 = k0b * k_k[c1];
    float s = q0 * q0 + q1 * q1;
#pragma unroll
    for (int off = 16; off > 0; off >>= 1) s += __shfl_xor_sync(0xffffffffu, s, off);
    float inv = 1.f / fmaxf(sqrtf(s), 1e-12f);
    float kk0 = q0 * inv, kk1 = q1 * inv;

    float a0 = g_a[base + lane], a1 = g_a[base + lane + 32];
    float kf0 = k0a * (1.f + (a0 - 1.f) * k_a[c0]);
    float kf1 = k0b * (1.f + (a1 - 1.f) * k_a[c1]);
    float m0 = expf(g_w[base + lane]), m1 = expf(g_w[base + lane + 32]);
    float r0 = g_r[base + lane], r1 = g_r[base + lane + 32];
    float b0 = kk0 * a0, b1 = kk1 * a1;

    g_m[base + lane] = m0;          g_m[base + lane + 32] = m1;
    g_ad[base + lane] = -kk0 * m0;  g_ad[base + lane + 32] = -kk1 * m1;
    g_rd[base + lane] = r0 * m0;    g_rd[base + lane + 32] = r1 * m1;
    g_bb[base + lane] = b0;         g_bb[base + lane + 32] = b1;
    g_kf[base + lane] = kf0;        g_kf[base + lane + 32] = kf1;

    float rb = r0 * b0 + r1 * b1;
    float rk = r0 * kf0 + r1 * kf1;
#pragma unroll
    for (int off = 16; off > 0; off >>= 1) {
        rb += __shfl_xor_sync(0xffffffffu, rb, off);
        rk += __shfl_xor_sync(0xffffffffu, rk, off);
    }
    if (lane == 0) { g_rb[gid] = rb; g_rk[gid] = rk; }
}

// ---------------- sequential WKV7 scan, column-parallel ---------------------
__global__ __launch_bounds__(128, 1) void scan_kernel(float* __restrict__ out) {
    const int bx = blockIdx.x;
    const int bh = bx >> 1, half = bx & 1;
    const int b = bh >> 4, h = bh & 15;
    const int tid = threadIdx.x;
    const int wid = tid >> 5, lane = tid & 31;
    const int c = lane & 7, dq = lane >> 3;
    const int e = half * 32 + wid * 8 + c;
    const int d0 = dq * 16;
    const int bT0 = b * Tn;

    __shared__ float sb[2][5][SS][64];
    __shared__ float sv[2][SS][32];
    __shared__ float sc[2][2][SS];

    float2 S[8];
#pragma unroll
    for (int i = 0; i < 8; i++) S[i] = make_float2(0.f, 0.f);

    const float* aps[5] = { g_m, g_ad, g_rd, g_bb, g_kf };

    auto stage = [&](int ss, int bufI) {
#pragma unroll
        for (int j = tid; j < 704; j += 128) {
            if (j < 640) {
                int arr = j >> 7, rem = j & 127, s = rem >> 4, f4 = rem & 15;
                const float* src = aps[arr] + ((size_t)(bT0 + ss * SS + s)) * Cn + h * Dn + f4 * 4;
                cpasync16(&sb[bufI][arr][s][f4 * 4], src, 16);
            } else {
                int jj = j - 640;
                int s = jj >> 3, f4 = jj & 7;
                const float* src = g_v + ((size_t)(bT0 + ss * SS + s)) * Cn + h * Dn + half * 32 + f4 * 4;
                cpasync16(&sv[bufI][s][f4 * 4], src, 16);
            }
        }
        if (tid < 16) {
            int arr = tid >> 3, s = tid & 7;
            const float* src = (arr ? g_rk : g_rb) + (size_t)(bT0 + ss * SS + s) * Hn + h;
            cpasync4(&sc[bufI][arr][s], src);
        }
        cpcommit();
    };

    stage(0, 0);

    for (int ss = 0; ss < Tn / SS; ss++) {
        const int cur = ss & 1;
        cpwait0();
        __syncthreads();
        if (ss + 1 < Tn / SS) stage(ss + 1, cur ^ 1);

#pragma unroll 2
        for (int s = 0; s < SS; s++) {
            float4 ad4[4], rd4[4];
#pragma unroll
            for (int i = 0; i < 4; i++) {
                ad4[i] = *(const float4*)&sb[cur][1][s][d0 + i * 4];
                rd4[i] = *(const float4*)&sb[cur][2][s][d0 + i * 4];
            }
            const float2* ad2 = (const float2*)ad4;
            const float2* rd2 = (const float2*)rd4;

            float2 tA = make_float2(0.f, 0.f), tB = make_float2(0.f, 0.f);
            float2 rA = make_float2(0.f, 0.f), rB = make_float2(0.f, 0.f);
#pragma unroll
            for (int i = 0; i < 8; i += 2) {
                tA = ffma2(ad2[i], S[i], tA);
                tB = ffma2(ad2[i + 1], S[i + 1], tB);
                rA = ffma2(rd2[i], S[i], rA);
                rB = ffma2(rd2[i + 1], S[i + 1], rB);
            }
            float ta = (tA.x + tB.x) + (tA.y + tB.y);
            float ro = (rA.x + rB.x) + (rA.y + rB.y);

            float4 m4[4], b4[4], k4[4];
#pragma unroll
            for (int i = 0; i < 4; i++) {
                m4[i] = *(const float4*)&sb[cur][0][s][d0 + i * 4];
                b4[i] = *(const float4*)&sb[cur][3][s][d0 + i * 4];
                k4[i] = *(const float4*)&sb[cur][4][s][d0 + i * 4];
            }
            float v = sv[cur][s][wid * 8 + c];
            float rb = sc[cur][0][s], rk = sc[cur][1][s];

            ta += __shfl_xor_sync(0xffffffffu, ta, 8);
            ro += __shfl_xor_sync(0xffffffffu, ro, 8);
            ta += __shfl_xor_sync(0xffffffffu, ta, 16);
            ro += __shfl_xor_sync(0xffffffffu, ro, 16);

            const float2* m2 = (const float2*)m4;
            const float2* b2 = (const float2*)b4;
            const float2* k2 = (const float2*)k4;
            float2 ta2 = make_float2(ta, ta), v2 = make_float2(v, v);
#pragma unroll
            for (int i = 0; i < 8; i++) {
                float2 t1 = fmul2(k2[i], v2);
                t1 = ffma2(b2[i], ta2, t1);
                S[i] = ffma2(m2[i], S[i], t1);
            }
            if (dq == 0) {
                out[((size_t)(bT0 + ss * SS + s)) * Cn + h * Dn + e] =
                    fmaf(rb, ta, fmaf(rk, v, ro));
            }
        }
    }
}

// ---------------- GroupNorm + corr + gate (writes fp16 g_y) ----------------
__global__ void post_kernel(const float* __restrict__ r_k, const float* __restrict__ gn_w,
                            const float* __restrict__ gn_b) {
    int gid = blockIdx.x * (blockDim.x >> 5) + (threadIdx.x >> 5);
    int lane = threadIdx.x & 31;
    if (gid >= Bn * Tn * Hn) return;
    size_t base = (size_t)(gid >> 4) * Cn + (gid & 15) * Dn;
    int h = gid & 15;
    int c0 = h * Dn + lane, c1 = c0 + 32;
    float o0 = g_osc[base + lane], o1 = g_osc[base + lane + 32];
    float s1 = o0 + o1;
    float s2 = o0 * o0 + o1 * o1;
    float rr0 = g_r[base + lane], rr1 = g_r[base + lane + 32];
    float kk0 = g_kf[base + lane], kk1 = g_kf[base + lane + 32];
    float dp = rr0 * kk0 * r_k[c0] + rr1 * kk1 * r_k[c1];
#pragma unroll
    for (int off = 16; off > 0; off >>= 1) {
        s1 += __shfl_xor_sync(0xffffffffu, s1, off);
        s2 += __shfl_xor_sync(0xffffffffu, s2, off);
        dp += __shfl_xor_sync(0xffffffffu, dp, off);
    }
    float mu = s1 * (1.f / 64.f);
    float var = s2 * (1.f / 64.f) - mu * mu;
    float inv = 1.f / sqrtf(var + GN_EPS);
    float v0 = g_v[base + lane], v1 = g_v[base + lane + 32];
    float y0 = ((o0 - mu) * inv * gn_w[c0] + gn_b[c0] + dp * v0) * g_g[base + lane];
    float y1 = ((o1 - mu) * inv * gn_w[c1] + gn_b[c1] + dp * v1) * g_g[base + lane + 32];
    g_y[base + lane] = __float2half_rn(y0);
    g_y[base + lane + 32] = __float2half_rn(y1);
}

// ---------------- launch ----------------------------------------------------
extern "C" void kernel_launch(void* const* d_in, const int* in_sizes, int n_in,
                              void* d_out, int out_size) {
    const float* hs     = (const float*)d_in[0];
    const float* vfirst = (const float*)d_in[1];
    const float* xmix   = (const float*)d_in[2];
    const float* k_k    = (const float*)d_in[3];
    const float* k_a    = (const float*)d_in[4];
    const float* r_k    = (const float*)d_in[5];
    const float* W_r    = (const float*)d_in[6];
    const float* W_k    = (const float*)d_in[7];
    const float* W_v    = (const float*)d_in[8];
    const float* W_o    = (const float*)d_in[9];
    const float* w_A    = (const float*)d_in[10];
    const float* w_B    = (const float*)d_in[11];
    const float* w_b    = (const float*)d_in[12];
    const float* a_A    = (const float*)d_in[13];
    const float* a_B    = (const float*)d_in[14];
    const float* a_b    = (const float*)d_in[15];
    const float* v_A    = (const float*)d_in[16];
    const float* v_B    = (const float*)d_in[17];
    const float* v_b    = (const float*)d_in[18];
    const float* g_Ain  = (const float*)d_in[19];
    const float* g_Bin  = (const float*)d_in[20];
    const float* gn_w   = (const float*)d_in[21];
    const float* gn_b   = (const float*)d_in[22];
    float* outp = (float*)d_out;

    __half *p_xr, *p_xw, *p_xk, *p_xv, *p_xa, *p_xg, *p_y;
    __half *p_tmpW, *p_tmpA, *p_tmpV, *p_tmpG, *p_wts;
    float *p_r, *p_k0, *p_v, *p_w, *p_a, *p_g, *p_osc;
    cudaGetSymbolAddress((void**)&p_xr, g_xr);
    cudaGetSymbolAddress((void**)&p_xw, g_xw);
    cudaGetSymbolAddress((void**)&p_xk, g_xk);
    cudaGetSymbolAddress((void**)&p_xv, g_xv);
    cudaGetSymbolAddress((void**)&p_xa, g_xa);
    cudaGetSymbolAddress((void**)&p_xg, g_xg);
    cudaGetSymbolAddress((void**)&p_r, g_r);
    cudaGetSymbolAddress((void**)&p_k0, g_k0);
    cudaGetSymbolAddress((void**)&p_v, g_v);
    cudaGetSymbolAddress((void**)&p_w, g_w);
    cudaGetSymbolAddress((void**)&p_a, g_a);
    cudaGetSymbolAddress((void**)&p_g, g_g);
    cudaGetSymbolAddress((void**)&p_osc, g_osc);
    cudaGetSymbolAddress((void**)&p_y, g_y);
    cudaGetSymbolAddress((void**)&p_tmpW, g_tmpW);
    cudaGetSymbolAddress((void**)&p_tmpA, g_tmpA);
    cudaGetSymbolAddress((void**)&p_tmpV, g_tmpV);
    cudaGetSymbolAddress((void**)&p_tmpG, g_tmpG);
    cudaGetSymbolAddress((void**)&p_wts, g_wts);

    const int SMEM = (PIPE * 128 * LDPh + PIPE * BNt * LDPh) * 2;   // 46080
    cudaFuncSetAttribute(gemmTC, cudaFuncAttributeMaxDynamicSharedMemorySize, SMEM);

    // 1. mix + weight fp16 conversion
    {
        int total4 = (NTOK + WTS_TOTAL) / 4;
        mixcvt_kernel<<<(total4 + 255) / 256, 256>>>(hs, xmix, W_r, W_k, W_v, W_o,
                                                     w_A, a_A, v_A, g_Ain,
                                                     w_B, a_B, v_B, g_Bin);
    }

    // 2. r, k0, v0 (z=3)
    {
        Jobs J;
        J.j[0] = { p_xr, p_wts + OFF_Wr, p_r,  nullptr, nullptr, nullptr, 0, Cn, Cn };
        J.j[1] = { p_xk, p_wts + OFF_Wk, p_k0, nullptr, nullptr, nullptr, 0, Cn, Cn };
        J.j[2] = { p_xv, p_wts + OFF_Wv, p_v,  nullptr, nullptr, nullptr, 0, Cn, Cn };
        J.j[3] = J.j[0];
        gemmTC<<<dim3(16, 16, 3), 256, SMEM>>>(J);
    }
    // 3. LoRA stage 1 for w,a,v,g (z=4) -> half outputs
    {
        Jobs J;
        J.j[0] = { p_xw, p_wts + OFF_wA, p_tmpW, nullptr, nullptr, nullptr, 1, W_LR, Cn };
        J.j[1] = { p_xa, p_wts + OFF_aA, p_tmpA, nullptr, nullptr, nullptr, 6, A_LR, Cn };
        J.j[2] = { p_xv, p_wts + OFF_vA, p_tmpV, nullptr, nullptr, nullptr, 6, V_LR, Cn };
        J.j[3] = { p_xg, p_wts + OFF_gA, p_tmpG, nullptr, nullptr, nullptr, 2, G_LR, Cn };
        gemmTC<<<dim3(3, 16, 4), 256, SMEM>>>(J);
    }
    // 4. LoRA stage 2 for w,a,v,g (z=4) -> fp32 outputs
    {
        Jobs J;
        J.j[0] = { p_tmpW, p_wts + OFF_wB, p_w, w_b, nullptr, nullptr, 4, Cn, W_LR };
        J.j[1] = { p_tmpA, p_wts + OFF_aB, p_a, a_b, nullptr, nullptr, 3, Cn, A_LR };
        J.j[2] = { p_tmpV, p_wts + OFF_vB, p_v, v_b, p_v, vfirst, 5, Cn, V_LR };
        J.j[3] = { p_tmpG, p_wts + OFF_gB, p_g, nullptr, nullptr, nullptr, 0, Cn, G_LR };
        gemmTC<<<dim3(16, 16, 4), 256, SMEM>>>(J);
    }
    // 5. prep (kk norm, k final, scan precomputes)
    prep_kernel<<<(BTn * Hn + 7) / 8, 256>>>(k_k, k_a);

    // 6. sequential scan
    scan_kernel<<<Bn * Hn * 2, 128>>>(p_osc);

    // 7. groupnorm + corr + gate -> fp16 y
    post_kernel<<<(Bn * Tn * Hn + 7) / 8, 256>>>(r_k, gn_w, gn_b);

    // 8. output projection (A = fp16 y)
    {
        Jobs J;
        J.j[0] = { p_y, p_wts + OFF_Wo, outp, nullptr, nullptr, nullptr, 0, Cn, Cn };
        J.j[1] = J.j[0]; J.j[2] = J.j[0]; J.j[3] = J.j[0];
        gemmTC<<<dim3(16, 16, 1), 256, SMEM>>>(J);
    }
}

// round 13
// speedup vs baseline: 1.0912x; 1.0912x over previous
#include <cuda_runtime.h>
#include <cuda_fp16.h>
#include <math.h>
#include <stdint.h>

// Problem dims
#define Bn 2
#define Tn 1024
#define Cn 1024
#define Hn 16
#define Dn 64
#define BTn (Bn * Tn)
#define NTOK (Bn * Tn * Cn)
#define W_LR 64
#define A_LR 64
#define V_LR 64
#define G_LR 160
#define DECAY_SCALE (-0.6065306597126334f)
#define GN_EPS (64.0f * 1e-5f)
#define SS 8

// fp16 weight scratch offsets (in elements)
#define OFF_Wr 0
#define OFF_Wk 1048576
#define OFF_Wv 2097152
#define OFF_Wo 3145728
#define OFF_wA 4194304
#define OFF_aA 4259840
#define OFF_vA 4325376
#define OFF_gA 4390912
#define OFF_wB 4554752
#define OFF_aB 4620288
#define OFF_vB 4685824
#define OFF_gB 4751360
#define WTS_TOTAL 4915200

// ---------------- scratch (__device__ globals) -----------------------------
__device__ __align__(16) __half g_xr[NTOK], g_xw[NTOK], g_xk[NTOK], g_xv[NTOK], g_xa[NTOK], g_xg[NTOK];
__device__ float g_r[NTOK], g_k0[NTOK], g_v[NTOK], g_w[NTOK], g_a[NTOK], g_g[NTOK];
__device__ float g_kf[NTOK];
__device__ float g_m[NTOK], g_ad[NTOK], g_rd[NTOK], g_bb[NTOK];
__device__ float g_rb[BTn * Hn], g_rk[BTn * Hn];
__device__ float g_osc[NTOK];
__device__ __align__(16) __half g_y[NTOK];
__device__ __align__(16) __half g_tmpW[BTn * W_LR], g_tmpA[BTn * A_LR], g_tmpV[BTn * V_LR], g_tmpG[BTn * G_LR];
__device__ __align__(16) __half g_wts[WTS_TOTAL];

// ---------------- helpers --------------------------------------------------
__device__ __forceinline__ float sigmoidf_(float x) { return 1.f / (1.f + expf(-x)); }

__device__ __forceinline__ void cpasync16(void* smem, const void* gptr, int srcbytes) {
    uint32_t s = (uint32_t)__cvta_generic_to_shared(smem);
    asm volatile("cp.async.ca.shared.global [%0], [%1], 16, %2;" :: "r"(s), "l"(gptr), "r"(srcbytes));
}
__device__ __forceinline__ void cpasync4(void* smem, const void* gptr) {
    uint32_t s = (uint32_t)__cvta_generic_to_shared(smem);
    asm volatile("cp.async.ca.shared.global [%0], [%1], 4;" :: "r"(s), "l"(gptr));
}
__device__ __forceinline__ void cpcommit() { asm volatile("cp.async.commit_group;"); }
__device__ __forceinline__ void cpwait1() { asm volatile("cp.async.wait_group 1;"); }
__device__ __forceinline__ void cpwait0() { asm volatile("cp.async.wait_group 0;"); }

__device__ __forceinline__ float2 ffma2(float2 a, float2 b, float2 c) {
    unsigned long long ua = *(unsigned long long*)&a;
    unsigned long long ub = *(unsigned long long*)&b;
    unsigned long long uc = *(unsigned long long*)&c;
    unsigned long long ud;
    asm("fma.rn.f32x2 %0, %1, %2, %3;" : "=l"(ud) : "l"(ua), "l"(ub), "l"(uc));
    return *(float2*)&ud;
}
__device__ __forceinline__ float2 fmul2(float2 a, float2 b) {
    unsigned long long ua = *(unsigned long long*)&a;
    unsigned long long ub = *(unsigned long long*)&b;
    unsigned long long ud;
    asm("mul.rn.f32x2 %0, %1, %2;" : "=l"(ud) : "l"(ua), "l"(ub));
    return *(float2*)&ud;
}

__device__ __forceinline__ void mma_f16(float* d, const uint32_t* a, const uint32_t* b) {
    asm volatile(
        "mma.sync.aligned.m16n8k16.row.col.f32.f16.f16.f32 "
        "{%0,%1,%2,%3}, {%4,%5,%6,%7}, {%8,%9}, {%0,%1,%2,%3};"
        : "+f"(d[0]), "+f"(d[1]), "+f"(d[2]), "+f"(d[3])
        : "r"(a[0]), "r"(a[1]), "r"(a[2]), "r"(a[3]), "r"(b[0]), "r"(b[1]));
}

// ---------------- mix + weight fp16 conversion, vectorized -----------------
__device__ __forceinline__ uint2 mix4h(float4 h, float4 d, const float* mxp) {
    float4 mx = *(const float4*)mxp;
    __half2 lo = __floats2half2_rn(fmaf(d.x, mx.x, h.x), fmaf(d.y, mx.y, h.y));
    __half2 hi = __floats2half2_rn(fmaf(d.z, mx.z, h.z), fmaf(d.w, mx.w, h.w));
    uint2 r;
    r.x = *(uint32_t*)&lo; r.y = *(uint32_t*)&hi;
    return r;
}

__global__ void mixcvt_kernel(const float* __restrict__ hs, const float* __restrict__ xmix,
                              const float* __restrict__ Wr, const float* __restrict__ Wk,
                              const float* __restrict__ Wv, const float* __restrict__ Wo,
                              const float* __restrict__ wA, const float* __restrict__ aA,
                              const float* __restrict__ vA, const float* __restrict__ gA,
                              const float* __restrict__ wB, const float* __restrict__ aB,
                              const float* __restrict__ vB, const float* __restrict__ gB) {
    int i4 = blockIdx.x * blockDim.x + threadIdx.x;
    const int NTOK4 = NTOK / 4;
    if (i4 < NTOK4) {
        int base = i4 * 4;
        int c = base & (Cn - 1);
        int t = (base / Cn) & (Tn - 1);
        float4 h = *(const float4*)(hs + base);
        float4 p = (t == 0) ? make_float4(0.f, 0.f, 0.f, 0.f)
                            : *(const float4*)(hs + base - Cn);
        float4 d = make_float4(p.x - h.x, p.y - h.y, p.z - h.z, p.w - h.w);
        *(uint2*)(g_xr + base) = mix4h(h, d, xmix + 0 * Cn + c);
        *(uint2*)(g_xw + base) = mix4h(h, d, xmix + 1 * Cn + c);
        *(uint2*)(g_xk + base) = mix4h(h, d, xmix + 2 * Cn + c);
        *(uint2*)(g_xv + base) = mix4h(h, d, xmix + 3 * Cn + c);
        *(uint2*)(g_xa + base) = mix4h(h, d, xmix + 4 * Cn + c);
        *(uint2*)(g_xg + base) = mix4h(h, d, xmix + 5 * Cn + c);
    } else {
        int j = (i4 - NTOK4) * 4;
        if (j >= WTS_TOTAL) return;
        const float* src;
        if (j < OFF_Wk)      src = Wr + (j - OFF_Wr);
        else if (j < OFF_Wv) src = Wk + (j - OFF_Wk);
        else if (j < OFF_Wo) src = Wv + (j - OFF_Wv);
        else if (j < OFF_wA) src = Wo + (j - OFF_Wo);
        else if (j < OFF_aA) src = wA + (j - OFF_wA);
        else if (j < OFF_vA) src = aA + (j - OFF_aA);
        else if (j < OFF_gA) src = vA + (j - OFF_vA);
        else if (j < OFF_wB) src = gA + (j - OFF_gA);
        else if (j < OFF_aB) src = wB + (j - OFF_wB);
        else if (j < OFF_vB) src = aB + (j - OFF_aB);
        else if (j < OFF_gB) src = vB + (j - OFF_vB);
        else                 src = gB + (j - OFF_gB);
        float4 v = *(const float4*)src;
        __half2 lo = __floats2half2_rn(v.x, v.y);
        __half2 hi = __floats2half2_rn(v.z, v.w);
        uint2 r; r.x = *(uint32_t*)&lo; r.y = *(uint32_t*)&hi;
        *(uint2*)(g_wts + j) = r;
    }
}

// ---------------- tensor-core fp16 GEMM, BM=128 BN=64 BK=32, 2-stage -------
// 8 warps as 4(M) x 2(N): WM=32 (MF=2), WN=32. acc = 32 regs/thread.
// epi: 0 plain fp32, 1 tanh->half, 2 sigmoid->half, 3 sigmoid(x+bias) fp32,
//      4 DECAY*sigmoid(x+bias) fp32, 5 lerp fp32, 6 plain->half
struct Job {
    const __half* A; const __half* W; void* O;
    const float* bias; const float* p1; const float* p2;
    int epi; int N; int K;
};
struct Jobs { Job j[7]; };

#define LDPh 40   // halves per smem row
#define BNt 64
#define MF 2

__global__ __launch_bounds__(256, 3) void gemmTC(Jobs jobs) {
    extern __shared__ __half hsm[];
    __half* As = hsm;                       // [2][128][LDPh]
    __half* Bs = hsm + 2 * 128 * LDPh;      // [2][64][LDPh]

    Job jb = jobs.j[blockIdx.z];
    const int N = jb.N, K = jb.K;
    const int row0 = blockIdx.y * 128;
    const int col0 = blockIdx.x * BNt;
    if (col0 >= N) return;
    const int tid = threadIdx.x;
    const int wid = tid >> 5, lane = tid & 31;
    const int wm = wid & 3, wn = wid >> 2;     // 4 x 2
    const int mbase = wm * 32, nbase = wn * 32;
    const int g = lane >> 2, q = lane & 3;

    const int arow = tid >> 1;
    const int ah0 = (tid & 1) * 16;

    auto stageTiles = [&](int kt, int b) {
        const __half* Ap = jb.A + (size_t)(row0 + arow) * K + kt * 32 + ah0;
        __half* Ad = &As[(b * 128 + arow) * LDPh + ah0];
        cpasync16(Ad + 0, Ap + 0, 16);
        cpasync16(Ad + 8, Ap + 8, 16);
        int brow = tid >> 2, bh0 = (tid & 3) * 8;
        int bn0 = col0 + brow;
        const __half* Bp = jb.W + (size_t)bn0 * K + kt * 32 + bh0;
        cpasync16(&Bs[(b * BNt + brow) * LDPh + bh0], Bp, (bn0 < N) ? 16 : 0);
        cpcommit();
    };

    float acc[MF][4][4];
#pragma unroll
    for (int i = 0; i < MF; i++)
#pragma unroll
        for (int j2 = 0; j2 < 4; j2++)
#pragma unroll
            for (int k2 = 0; k2 < 4; k2++) acc[i][j2][k2] = 0.f;

    const int nk = K >> 5;

    stageTiles(0, 0);

    for (int kt = 0; kt < nk; kt++) {
        const int buf = kt & 1;
        if (kt + 1 < nk) {
            stageTiles(kt + 1, buf ^ 1);
            cpwait1();
        } else {
            cpwait0();
        }
        __syncthreads();

        const uint32_t* Au = (const uint32_t*)(As + buf * 128 * LDPh);
        const uint32_t* Bu = (const uint32_t*)(Bs + buf * BNt * LDPh);
#pragma unroll
        for (int kw = 0; kw < 16; kw += 8) {
            uint32_t af[MF][4], bf[4][2];
#pragma unroll
            for (int mf = 0; mf < MF; mf++) {
                int m = mbase + mf * 16 + g;
                af[mf][0] = Au[m * (LDPh / 2) + kw + q];
                af[mf][1] = Au[(m + 8) * (LDPh / 2) + kw + q];
                af[mf][2] = Au[m * (LDPh / 2) + kw + q + 4];
                af[mf][3] = Au[(m + 8) * (LDPh / 2) + kw + q + 4];
            }
#pragma unroll
            for (int nf = 0; nf < 4; nf++) {
                int n = nbase + nf * 8 + g;
                bf[nf][0] = Bu[n * (LDPh / 2) + kw + q];
                bf[nf][1] = Bu[n * (LDPh / 2) + kw + q + 4];
            }
#pragma unroll
            for (int mf = 0; mf < MF; mf++)
#pragma unroll
                for (int nf = 0; nf < 4; nf++) mma_f16(acc[mf][nf], af[mf], bf[nf]);
        }
        __syncthreads();
    }

    const int epi = jb.epi;
#pragma unroll
    for (int mf = 0; mf < MF; mf++) {
#pragma unroll
        for (int nf = 0; nf < 4; nf++) {
            int r0 = row0 + mbase + mf * 16 + g;
            int c = col0 + nbase + nf * 8 + 2 * q;
            if (c >= N) continue;
#pragma unroll
            for (int rr = 0; rr < 2; rr++) {
                int r = r0 + rr * 8;
                float x0 = acc[mf][nf][rr * 2 + 0];
                float x1 = acc[mf][nf][rr * 2 + 1];
                if (epi == 0) {
                    *(float2*)((float*)jb.O + (size_t)r * N + c) = make_float2(x0, x1);
                } else if (epi == 6) {
                    __half2 hv = __floats2half2_rn(x0, x1);
                    *(__half2*)((__half*)jb.O + (size_t)r * N + c) = hv;
                } else if (epi == 1) {
                    __half2 hv = __floats2half2_rn(tanhf(x0), tanhf(x1));
                    *(__half2*)((__half*)jb.O + (size_t)r * N + c) = hv;
                } else if (epi == 2) {
                    __half2 hv = __floats2half2_rn(sigmoidf_(x0), sigmoidf_(x1));
                    *(__half2*)((__half*)jb.O + (size_t)r * N + c) = hv;
                } else if (epi == 3) {
                    float y0 = sigmoidf_(x0 + __ldg(jb.bias + c));
                    float y1 = sigmoidf_(x1 + __ldg(jb.bias + c + 1));
                    *(float2*)((float*)jb.O + (size_t)r * N + c) = make_float2(y0, y1);
                } else if (epi == 4) {
                    float y0 = DECAY_SCALE * sigmoidf_(x0 + __ldg(jb.bias + c));
                    float y1 = DECAY_SCALE * sigmoidf_(x1 + __ldg(jb.bias + c + 1));
                    *(float2*)((float*)jb.O + (size_t)r * N + c) = make_float2(y0, y1);
                } else { // 5
                    size_t i0 = (size_t)r * N + c;
                    float s0 = sigmoidf_(x0 + __ldg(jb.bias + c));
                    float s1 = sigmoidf_(x1 + __ldg(jb.bias + c + 1));
                    float a0 = jb.p1[i0], b0 = jb.p2[i0];
                    float a1 = jb.p1[i0 + 1], b1 = jb.p2[i0 + 1];
                    float y0 = fmaf(s0, b0 - a0, a0);
                    float y1 = fmaf(s1, b1 - a1, a1);
                    *(float2*)((float*)jb.O + i0) = make_float2(y0, y1);
                }
            }
        }
    }
}

// ---------------- prep: kk-normalize, k-final, scan precomputes ------------
__global__ void prep_kernel(const float* __restrict__ k_k, const float* __restrict__ k_a) {
    int gid = blockIdx.x * (blockDim.x >> 5) + (threadIdx.x >> 5);
    int lane = threadIdx.x & 31;
    if (gid >= BTn * Hn) return;
    int bt = gid >> 4, h = gid & 15;
    size_t base = (size_t)bt * Cn + h * Dn;
    int c0 = h * Dn + lane, c1 = c0 + 32;

    float k0a = g_k0[base + lane], k0b = g_k0[base + lane + 32];
    float q0 = k0a * k_k[c0], q1 = k0b * k_k[c1];
    float s = q0 * q0 + q1 * q1;
#pragma unroll
    for (int off = 16; off > 0; off >>= 1) s += __shfl_xor_sync(0xffffffffu, s, off);
    float inv = 1.f / fmaxf(sqrtf(s), 1e-12f);
    float kk0 = q0 * inv, kk1 = q1 * inv;

    float a0 = g_a[base + lane], a1 = g_a[base + lane + 32];
    float kf0 = k0a * (1.f + (a0 - 1.f) * k_a[c0]);
    float kf1 = k0b * (1.f + (a1 - 1.f) * k_a[c1]);
    float m0 = expf(g_w[base + lane]), m1 = expf(g_w[base + lane + 32]);
    float r0 = g_r[base + lane], r1 = g_r[base + lane + 32];
    float b0 = kk0 * a0, b1 = kk1 * a1;

    g_m[base + lane] = m0;          g_m[base + lane + 32] = m1;
    g_ad[base + lane] = -kk0 * m0;  g_ad[base + lane + 32] = -kk1 * m1;
    g_rd[base + lane] = r0 * m0;    g_rd[base + lane + 32] = r1 * m1;
    g_bb[base + lane] = b0;         g_bb[base + lane + 32] = b1;
    g_kf[base + lane] = kf0;        g_kf[base + lane + 32] = kf1;

    float rb = r0 * b0 + r1 * b1;
    float rk = r0 * kf0 + r1 * kf1;
#pragma unroll
    for (int off = 16; off > 0; off >>= 1) {
        rb += __shfl_xor_sync(0xffffffffu, rb, off);
        rk += __shfl_xor_sync(0xffffffffu, rk, off);
    }
    if (lane == 0) { g_rb[gid] = rb; g_rk[gid] = rk; }
}

// ---------------- sequential WKV7 scan, column-parallel ---------------------
__global__ __launch_bounds__(128, 1) void scan_kernel(float* __restrict__ out) {
    const int bx = blockIdx.x;
    const int bh = bx >> 1, half = bx & 1;
    const int b = bh >> 4, h = bh & 15;
    const int tid = threadIdx.x;
    const int wid = tid >> 5, lane = tid & 31;
    const int c = lane & 7, dq = lane >> 3;
    const int e = half * 32 + wid * 8 + c;
    const int d0 = dq * 16;
    const int bT0 = b * Tn;

    __shared__ float sb[2][5][SS][64];
    __shared__ float sv[2][SS][32];
    __shared__ float sc[2][2][SS];

    float2 S[8];
#pragma unroll
    for (int i = 0; i < 8; i++) S[i] = make_float2(0.f, 0.f);

    const float* aps[5] = { g_m, g_ad, g_rd, g_bb, g_kf };

    auto stage = [&](int ss, int bufI) {
#pragma unroll
        for (int j = tid; j < 704; j += 128) {
            if (j < 640) {
                int arr = j >> 7, rem = j & 127, s = rem >> 4, f4 = rem & 15;
                const float* src = aps[arr] + ((size_t)(bT0 + ss * SS + s)) * Cn + h * Dn + f4 * 4;
                cpasync16(&sb[bufI][arr][s][f4 * 4], src, 16);
            } else {
                int jj = j - 640;
                int s = jj >> 3, f4 = jj & 7;
                const float* src = g_v + ((size_t)(bT0 + ss * SS + s)) * Cn + h * Dn + half * 32 + f4 * 4;
                cpasync16(&sv[bufI][s][f4 * 4], src, 16);
            }
        }
        if (tid < 16) {
            int arr = tid >> 3, s = tid & 7;
            const float* src = (arr ? g_rk : g_rb) + (size_t)(bT0 + ss * SS + s) * Hn + h;
            cpasync4(&sc[bufI][arr][s], src);
        }
        cpcommit();
    };

    stage(0, 0);

    for (int ss = 0; ss < Tn / SS; ss++) {
        const int cur = ss & 1;
        cpwait0();
        __syncthreads();
        if (ss + 1 < Tn / SS) stage(ss + 1, cur ^ 1);

#pragma unroll 2
        for (int s = 0; s < SS; s++) {
            float4 ad4[4], rd4[4];
#pragma unroll
            for (int i = 0; i < 4; i++) {
                ad4[i] = *(const float4*)&sb[cur][1][s][d0 + i * 4];
                rd4[i] = *(const float4*)&sb[cur][2][s][d0 + i * 4];
            }
            const float2* ad2 = (const float2*)ad4;
            const float2* rd2 = (const float2*)rd4;

            float2 tA = make_float2(0.f, 0.f), tB = make_float2(0.f, 0.f);
            float2 rA = make_float2(0.f, 0.f), rB = make_float2(0.f, 0.f);
#pragma unroll
            for (int i = 0; i < 8; i += 2) {
                tA = ffma2(ad2[i], S[i], tA);
                tB = ffma2(ad2[i + 1], S[i + 1], tB);
                rA = ffma2(rd2[i], S[i], rA);
                rB = ffma2(rd2[i + 1], S[i + 1], rB);
            }
            float ta = (tA.x + tB.x) + (tA.y + tB.y);
            float ro = (rA.x + rB.x) + (rA.y + rB.y);

            float4 m4[4], b4[4], k4[4];
#pragma unroll
            for (int i = 0; i < 4; i++) {
                m4[i] = *(const float4*)&sb[cur][0][s][d0 + i * 4];
                b4[i] = *(const float4*)&sb[cur][3][s][d0 + i * 4];
                k4[i] = *(const float4*)&sb[cur][4][s][d0 + i * 4];
            }
            float v = sv[cur][s][wid * 8 + c];
            float rb = sc[cur][0][s], rk = sc[cur][1][s];

            ta += __shfl_xor_sync(0xffffffffu, ta, 8);
            ro += __shfl_xor_sync(0xffffffffu, ro, 8);
            ta += __shfl_xor_sync(0xffffffffu, ta, 16);
            ro += __shfl_xor_sync(0xffffffffu, ro, 16);

            const float2* m2 = (const float2*)m4;
            const float2* b2 = (const float2*)b4;
            const float2* k2 = (const float2*)k4;
            float2 ta2 = make_float2(ta, ta), v2 = make_float2(v, v);
#pragma unroll
            for (int i = 0; i < 8; i++) {
                float2 t1 = fmul2(k2[i], v2);
                t1 = ffma2(b2[i], ta2, t1);
                S[i] = ffma2(m2[i], S[i], t1);
            }
            if (dq == 0) {
                out[((size_t)(bT0 + ss * SS + s)) * Cn + h * Dn + e] =
                    fmaf(rb, ta, fmaf(rk, v, ro));
            }
        }
    }
}

// ---------------- GroupNorm + corr + gate (writes fp16 g_y) ----------------
__global__ void post_kernel(const float* __restrict__ r_k, const float* __restrict__ gn_w,
                            const float* __restrict__ gn_b) {
    int gid = blockIdx.x * (blockDim.x >> 5) + (threadIdx.x >> 5);
    int lane = threadIdx.x & 31;
    if (gid >= Bn * Tn * Hn) return;
    size_t base = (size_t)(gid >> 4) * Cn + (gid & 15) * Dn;
    int h = gid & 15;
    int c0 = h * Dn + lane, c1 = c0 + 32;
    float o0 = g_osc[base + lane], o1 = g_osc[base + lane + 32];
    float s1 = o0 + o1;
    float s2 = o0 * o0 + o1 * o1;
    float rr0 = g_r[base + lane], rr1 = g_r[base + lane + 32];
    float kk0 = g_kf[base + lane], kk1 = g_kf[base + lane + 32];
    float dp = rr0 * kk0 * r_k[c0] + rr1 * kk1 * r_k[c1];
#pragma unroll
    for (int off = 16; off > 0; off >>= 1) {
        s1 += __shfl_xor_sync(0xffffffffu, s1, off);
        s2 += __shfl_xor_sync(0xffffffffu, s2, off);
        dp += __shfl_xor_sync(0xffffffffu, dp, off);
    }
    float mu = s1 * (1.f / 64.f);
    float var = s2 * (1.f / 64.f) - mu * mu;
    float inv = 1.f / sqrtf(var + GN_EPS);
    float v0 = g_v[base + lane], v1 = g_v[base + lane + 32];
    float y0 = ((o0 - mu) * inv * gn_w[c0] + gn_b[c0] + dp * v0) * g_g[base + lane];
    float y1 = ((o1 - mu) * inv * gn_w[c1] + gn_b[c1] + dp * v1) * g_g[base + lane + 32];
    g_y[base + lane] = __float2half_rn(y0);
    g_y[base + lane + 32] = __float2half_rn(y1);
}

// ---------------- launch ----------------------------------------------------
extern "C" void kernel_launch(void* const* d_in, const int* in_sizes, int n_in,
                              void* d_out, int out_size) {
    const float* hs     = (const float*)d_in[0];
    const float* vfirst = (const float*)d_in[1];
    const float* xmix   = (const float*)d_in[2];
    const float* k_k    = (const float*)d_in[3];
    const float* k_a    = (const float*)d_in[4];
    const float* r_k    = (const float*)d_in[5];
    const float* W_r    = (const float*)d_in[6];
    const float* W_k    = (const float*)d_in[7];
    const float* W_v    = (const float*)d_in[8];
    const float* W_o    = (const float*)d_in[9];
    const float* w_A    = (const float*)d_in[10];
    const float* w_B    = (const float*)d_in[11];
    const float* w_b    = (const float*)d_in[12];
    const float* a_A    = (const float*)d_in[13];
    const float* a_B    = (const float*)d_in[14];
    const float* a_b    = (const float*)d_in[15];
    const float* v_A    = (const float*)d_in[16];
    const float* v_B    = (const float*)d_in[17];
    const float* v_b    = (const float*)d_in[18];
    const float* g_Ain  = (const float*)d_in[19];
    const float* g_Bin  = (const float*)d_in[20];
    const float* gn_w   = (const float*)d_in[21];
    const float* gn_b   = (const float*)d_in[22];
    float* outp = (float*)d_out;

    __half *p_xr, *p_xw, *p_xk, *p_xv, *p_xa, *p_xg, *p_y;
    __half *p_tmpW, *p_tmpA, *p_tmpV, *p_tmpG, *p_wts;
    float *p_r, *p_k0, *p_v, *p_w, *p_a, *p_g, *p_osc;
    cudaGetSymbolAddress((void**)&p_xr, g_xr);
    cudaGetSymbolAddress((void**)&p_xw, g_xw);
    cudaGetSymbolAddress((void**)&p_xk, g_xk);
    cudaGetSymbolAddress((void**)&p_xv, g_xv);
    cudaGetSymbolAddress((void**)&p_xa, g_xa);
    cudaGetSymbolAddress((void**)&p_xg, g_xg);
    cudaGetSymbolAddress((void**)&p_r, g_r);
    cudaGetSymbolAddress((void**)&p_k0, g_k0);
    cudaGetSymbolAddress((void**)&p_v, g_v);
    cudaGetSymbolAddress((void**)&p_w, g_w);
    cudaGetSymbolAddress((void**)&p_a, g_a);
    cudaGetSymbolAddress((void**)&p_g, g_g);
    cudaGetSymbolAddress((void**)&p_osc, g_osc);
    cudaGetSymbolAddress((void**)&p_y, g_y);
    cudaGetSymbolAddress((void**)&p_tmpW, g_tmpW);
    cudaGetSymbolAddress((void**)&p_tmpA, g_tmpA);
    cudaGetSymbolAddress((void**)&p_tmpV, g_tmpV);
    cudaGetSymbolAddress((void**)&p_tmpG, g_tmpG);
    cudaGetSymbolAddress((void**)&p_wts, g_wts);

    const int SMEM = (2 * 128 * LDPh + 2 * BNt * LDPh) * 2;   // 30720
    cudaFuncSetAttribute(gemmTC, cudaFuncAttributeMaxDynamicSharedMemorySize, SMEM);

    // 1. mix + weight fp16 conversion
    {
        int total4 = (NTOK + WTS_TOTAL) / 4;
        mixcvt_kernel<<<(total4 + 255) / 256, 256>>>(hs, xmix, W_r, W_k, W_v, W_o,
                                                     w_A, a_A, v_A, g_Ain,
                                                     w_B, a_B, v_B, g_Bin);
    }

    // 2. merged r/k/v + LoRA stage 1 (z=7; small-N jobs early-exit extra cols)
    {
        Jobs J;
        J.j[0] = { p_xr, p_wts + OFF_Wr, p_r,    nullptr, nullptr, nullptr, 0, Cn,   Cn };
        J.j[1] = { p_xk, p_wts + OFF_Wk, p_k0,   nullptr, nullptr, nullptr, 0, Cn,   Cn };
        J.j[2] = { p_xv, p_wts + OFF_Wv, p_v,    nullptr, nullptr, nullptr, 0, Cn,   Cn };
        J.j[3] = { p_xw, p_wts + OFF_wA, p_tmpW, nullptr, nullptr, nullptr, 1, W_LR, Cn };
        J.j[4] = { p_xa, p_wts + OFF_aA, p_tmpA, nullptr, nullptr, nullptr, 6, A_LR, Cn };
        J.j[5] = { p_xv, p_wts + OFF_vA, p_tmpV, nullptr, nullptr, nullptr, 6, V_LR, Cn };
        J.j[6] = { p_xg, p_wts + OFF_gA, p_tmpG, nullptr, nullptr, nullptr, 2, G_LR, Cn };
        gemmTC<<<dim3(16, 16, 7), 256, SMEM>>>(J);
    }
    // 3. LoRA stage 2 for w,a,v,g (z=4) -> fp32 outputs
    {
        Jobs J;
        J.j[0] = { p_tmpW, p_wts + OFF_wB, p_w, w_b, nullptr, nullptr, 4, Cn, W_LR };
        J.j[1] = { p_tmpA, p_wts + OFF_aB, p_a, a_b, nullptr, nullptr, 3, Cn, A_LR };
        J.j[2] = { p_tmpV, p_wts + OFF_vB, p_v, v_b, p_v, vfirst, 5, Cn, V_LR };
        J.j[3] = { p_tmpG, p_wts + OFF_gB, p_g, nullptr, nullptr, nullptr, 0, Cn, G_LR };
        gemmTC<<<dim3(16, 16, 4), 256, SMEM>>>(J);
    }
    // 4. prep (kk norm, k final, scan precomputes)
    prep_kernel<<<(BTn * Hn + 7) / 8, 256>>>(k_k, k_a);

    // 5. sequential scan
    scan_kernel<<<Bn * Hn * 2, 128>>>(p_osc);

    // 6. groupnorm + corr + gate -> fp16 y
    post_kernel<<<(Bn * Tn * Hn + 7) / 8, 256>>>(r_k, gn_w, gn_b);

    // 7. output projection (A = fp16 y)
    {
        Jobs J;
        J.j[0] = { p_y, p_wts + OFF_Wo, outp, nullptr, nullptr, nullptr, 0, Cn, Cn };
        J.j[1] = J.j[0]; J.j[2] = J.j[0]; J.j[3] = J.j[0];
        J.j[4] = J.j[0]; J.j[5] = J.j[0]; J.j[6] = J.j[0];
        gemmTC<<<dim3(16, 16, 1), 256, SMEM>>>(J);
    }
}

// round 14
// speedup vs baseline: 1.1576x; 1.0608x over previous
#include <cuda_runtime.h>
#include <cuda_fp16.h>
#include <math.h>
#include <stdint.h>

// Problem dims
#define Bn 2
#define Tn 1024
#define Cn 1024
#define Hn 16
#define Dn 64
#define BTn (Bn * Tn)
#define NTOK (Bn * Tn * Cn)
#define W_LR 64
#define A_LR 64
#define V_LR 64
#define G_LR 160
#define DECAY_SCALE (-0.6065306597126334f)
#define GN_EPS (64.0f * 1e-5f)
#define SS 8

// fp16 weight scratch offsets (in elements)
#define OFF_Wr 0
#define OFF_Wk 1048576
#define OFF_Wv 2097152
#define OFF_Wo 3145728
#define OFF_wA 4194304
#define OFF_aA 4259840
#define OFF_vA 4325376
#define OFF_gA 4390912
#define OFF_wB 4554752
#define OFF_aB 4620288
#define OFF_vB 4685824
#define OFF_gB 4751360
#define WTS_TOTAL 4915200

// ---------------- scratch (__device__ globals) -----------------------------
__device__ __align__(16) __half g_xr[NTOK], g_xw[NTOK], g_xk[NTOK], g_xv[NTOK], g_xa[NTOK], g_xg[NTOK];
__device__ float g_r[NTOK], g_k0[NTOK], g_v[NTOK], g_w[NTOK], g_a[NTOK], g_g[NTOK];
__device__ float g_kf[NTOK];
__device__ float g_m[NTOK], g_ad[NTOK], g_rd[NTOK], g_bb[NTOK];
__device__ float g_rb[BTn * Hn], g_rk[BTn * Hn];
__device__ float g_osc[NTOK];
__device__ __align__(16) __half g_y[NTOK];
__device__ __align__(16) __half g_tmpW[BTn * W_LR], g_tmpA[BTn * A_LR], g_tmpV[BTn * V_LR], g_tmpG[BTn * G_LR];
__device__ __align__(16) __half g_wts[WTS_TOTAL];

// ---------------- helpers --------------------------------------------------
__device__ __forceinline__ float sigmoidf_(float x) { return 1.f / (1.f + expf(-x)); }

__device__ __forceinline__ void cpasync16(void* smem, const void* gptr, int srcbytes) {
    uint32_t s = (uint32_t)__cvta_generic_to_shared(smem);
    asm volatile("cp.async.ca.shared.global [%0], [%1], 16, %2;" :: "r"(s), "l"(gptr), "r"(srcbytes));
}
__device__ __forceinline__ void cpasync4(void* smem, const void* gptr) {
    uint32_t s = (uint32_t)__cvta_generic_to_shared(smem);
    asm volatile("cp.async.ca.shared.global [%0], [%1], 4;" :: "r"(s), "l"(gptr));
}
__device__ __forceinline__ void cpcommit() { asm volatile("cp.async.commit_group;"); }
__device__ __forceinline__ void cpwait1() { asm volatile("cp.async.wait_group 1;"); }
__device__ __forceinline__ void cpwait0() { asm volatile("cp.async.wait_group 0;"); }

__device__ __forceinline__ float2 ffma2(float2 a, float2 b, float2 c) {
    unsigned long long ua = *(unsigned long long*)&a;
    unsigned long long ub = *(unsigned long long*)&b;
    unsigned long long uc = *(unsigned long long*)&c;
    unsigned long long ud;
    asm("fma.rn.f32x2 %0, %1, %2, %3;" : "=l"(ud) : "l"(ua), "l"(ub), "l"(uc));
    return *(float2*)&ud;
}
__device__ __forceinline__ float2 fmul2(float2 a, float2 b) {
    unsigned long long ua = *(unsigned long long*)&a;
    unsigned long long ub = *(unsigned long long*)&b;
    unsigned long long ud;
    asm("mul.rn.f32x2 %0, %1, %2;" : "=l"(ud) : "l"(ua), "l"(ub));
    return *(float2*)&ud;
}

__device__ __forceinline__ void mma_f16(float* d, const uint32_t* a, const uint32_t* b) {
    asm volatile(
        "mma.sync.aligned.m16n8k16.row.col.f32.f16.f16.f32 "
        "{%0,%1,%2,%3}, {%4,%5,%6,%7}, {%8,%9}, {%0,%1,%2,%3};"
        : "+f"(d[0]), "+f"(d[1]), "+f"(d[2]), "+f"(d[3])
        : "r"(a[0]), "r"(a[1]), "r"(a[2]), "r"(a[3]), "r"(b[0]), "r"(b[1]));
}

__device__ __forceinline__ void ldsm_x4(uint32_t* r, uint32_t saddr) {
    asm volatile("ldmatrix.sync.aligned.m8n8.x4.shared.b16 {%0,%1,%2,%3}, [%4];"
        : "=r"(r[0]), "=r"(r[1]), "=r"(r[2]), "=r"(r[3]) : "r"(saddr));
}
__device__ __forceinline__ void ldsm_x2(uint32_t* r, uint32_t saddr) {
    asm volatile("ldmatrix.sync.aligned.m8n8.x2.shared.b16 {%0,%1}, [%2];"
        : "=r"(r[0]), "=r"(r[1]) : "r"(saddr));
}

// ---------------- mix + weight fp16 conversion, vectorized -----------------
__device__ __forceinline__ uint2 mix4h(float4 h, float4 d, const float* mxp) {
    float4 mx = *(const float4*)mxp;
    __half2 lo = __floats2half2_rn(fmaf(d.x, mx.x, h.x), fmaf(d.y, mx.y, h.y));
    __half2 hi = __floats2half2_rn(fmaf(d.z, mx.z, h.z), fmaf(d.w, mx.w, h.w));
    uint2 r;
    r.x = *(uint32_t*)&lo; r.y = *(uint32_t*)&hi;
    return r;
}

__global__ void mixcvt_kernel(const float* __restrict__ hs, const float* __restrict__ xmix,
                              const float* __restrict__ Wr, const float* __restrict__ Wk,
                              const float* __restrict__ Wv, const float* __restrict__ Wo,
                              const float* __restrict__ wA, const float* __restrict__ aA,
                              const float* __restrict__ vA, const float* __restrict__ gA,
                              const float* __restrict__ wB, const float* __restrict__ aB,
                              const float* __restrict__ vB, const float* __restrict__ gB) {
    int i4 = blockIdx.x * blockDim.x + threadIdx.x;
    const int NTOK4 = NTOK / 4;
    if (i4 < NTOK4) {
        int base = i4 * 4;
        int c = base & (Cn - 1);
        int t = (base / Cn) & (Tn - 1);
        float4 h = *(const float4*)(hs + base);
        float4 p = (t == 0) ? make_float4(0.f, 0.f, 0.f, 0.f)
                            : *(const float4*)(hs + base - Cn);
        float4 d = make_float4(p.x - h.x, p.y - h.y, p.z - h.z, p.w - h.w);
        *(uint2*)(g_xr + base) = mix4h(h, d, xmix + 0 * Cn + c);
        *(uint2*)(g_xw + base) = mix4h(h, d, xmix + 1 * Cn + c);
        *(uint2*)(g_xk + base) = mix4h(h, d, xmix + 2 * Cn + c);
        *(uint2*)(g_xv + base) = mix4h(h, d, xmix + 3 * Cn + c);
        *(uint2*)(g_xa + base) = mix4h(h, d, xmix + 4 * Cn + c);
        *(uint2*)(g_xg + base) = mix4h(h, d, xmix + 5 * Cn + c);
    } else {
        int j = (i4 - NTOK4) * 4;
        if (j >= WTS_TOTAL) return;
        const float* src;
        if (j < OFF_Wk)      src = Wr + (j - OFF_Wr);
        else if (j < OFF_Wv) src = Wk + (j - OFF_Wk);
        else if (j < OFF_Wo) src = Wv + (j - OFF_Wv);
        else if (j < OFF_wA) src = Wo + (j - OFF_Wo);
        else if (j < OFF_aA) src = wA + (j - OFF_wA);
        else if (j < OFF_vA) src = aA + (j - OFF_aA);
        else if (j < OFF_gA) src = vA + (j - OFF_vA);
        else if (j < OFF_wB) src = gA + (j - OFF_gA);
        else if (j < OFF_aB) src = wB + (j - OFF_wB);
        else if (j < OFF_vB) src = aB + (j - OFF_aB);
        else if (j < OFF_gB) src = vB + (j - OFF_vB);
        else                 src = gB + (j - OFF_gB);
        float4 v = *(const float4*)src;
        __half2 lo = __floats2half2_rn(v.x, v.y);
        __half2 hi = __floats2half2_rn(v.z, v.w);
        uint2 r; r.x = *(uint32_t*)&lo; r.y = *(uint32_t*)&hi;
        *(uint2*)(g_wts + j) = r;
    }
}

// ---------------- tensor-core fp16 GEMM, BM=128 BN=64 BK=32, ldmatrix ------
// 8 warps as 4(M) x 2(N): WM=32 (MF=2), WN=32. acc = 32 regs/thread.
struct Job {
    const __half* A; const __half* W; void* O;
    const float* bias; const float* p1; const float* p2;
    int epi; int N; int K;
};
struct Jobs { Job j[7]; };

#define LDPh 40    // halves per smem row (20 words; 8-row ldmatrix tiles conflict-free)
#define BNt 64
#define MF 2

__global__ __launch_bounds__(256, 3) void gemmTC(Jobs jobs) {
    extern __shared__ __half hsm[];
    __half* As = hsm;                       // [2][128][LDPh]
    __half* Bs = hsm + 2 * 128 * LDPh;      // [2][64][LDPh]

    Job jb = jobs.j[blockIdx.z];
    const int N = jb.N, K = jb.K;
    const int row0 = blockIdx.y * 128;
    const int col0 = blockIdx.x * BNt;
    if (col0 >= N) return;
    const int tid = threadIdx.x;
    const int wid = tid >> 5, lane = tid & 31;
    const int wm = wid & 3, wn = wid >> 2;     // 4 x 2
    const int mbase = wm * 32, nbase = wn * 32;
    const int g = lane >> 2, q = lane & 3;

    const int arow = tid >> 1;
    const int ah0 = (tid & 1) * 16;

    auto stageTiles = [&](int kt, int b) {
        const __half* Ap = jb.A + (size_t)(row0 + arow) * K + kt * 32 + ah0;
        __half* Ad = &As[(b * 128 + arow) * LDPh + ah0];
        cpasync16(Ad + 0, Ap + 0, 16);
        cpasync16(Ad + 8, Ap + 8, 16);
        int brow = tid >> 2, bh0 = (tid & 3) * 8;
        int bn0 = col0 + brow;
        const __half* Bp = jb.W + (size_t)bn0 * K + kt * 32 + bh0;
        cpasync16(&Bs[(b * BNt + brow) * LDPh + bh0], Bp, (bn0 < N) ? 16 : 0);
        cpcommit();
    };

    float acc[MF][4][4];
#pragma unroll
    for (int i = 0; i < MF; i++)
#pragma unroll
        for (int j2 = 0; j2 < 4; j2++)
#pragma unroll
            for (int k2 = 0; k2 < 4; k2++) acc[i][j2][k2] = 0.f;

    const int nk = K >> 5;

    // ldmatrix lane-derived offsets (word units)
    const int l7 = lane & 7, lb3 = (lane >> 3) & 1, lb4 = (lane >> 4) & 1;
    const uint32_t sAbase = (uint32_t)__cvta_generic_to_shared(As);
    const uint32_t sBbase = (uint32_t)__cvta_generic_to_shared(Bs);
    // A x4: row = mbase + mf*16 + l7 + lb3*8 ; word = kw + lb4*4
    const uint32_t aOffW = (uint32_t)((mbase + l7 + lb3 * 8) * 20 + lb4 * 4);
    // B x2: row = nbase + nf*8 + (lane&7 of lanes0-15) ; word = kw + lb3*4
    const uint32_t bOffW = (uint32_t)((nbase + l7) * 20 + lb3 * 4);

    stageTiles(0, 0);

    for (int kt = 0; kt < nk; kt++) {
        const int buf = kt & 1;
        if (kt + 1 < nk) {
            stageTiles(kt + 1, buf ^ 1);
            cpwait1();
        } else {
            cpwait0();
        }
        __syncthreads();

        const uint32_t aB0 = sAbase + (buf * 128 * 20 + aOffW) * 4;
        const uint32_t bB0 = sBbase + (buf * BNt * 20 + bOffW) * 4;
#pragma unroll
        for (int kw = 0; kw < 16; kw += 8) {
            uint32_t af[MF][4], bf[4][2];
#pragma unroll
            for (int mf = 0; mf < MF; mf++)
                ldsm_x4(af[mf], aB0 + (mf * 16 * 20 + kw) * 4);
#pragma unroll
            for (int nf = 0; nf < 4; nf++)
                ldsm_x2(bf[nf], bB0 + (nf * 8 * 20 + kw) * 4);
#pragma unroll
            for (int mf = 0; mf < MF; mf++)
#pragma unroll
                for (int nf = 0; nf < 4; nf++) mma_f16(acc[mf][nf], af[mf], bf[nf]);
        }
        __syncthreads();
    }

    const int epi = jb.epi;
#pragma unroll
    for (int mf = 0; mf < MF; mf++) {
#pragma unroll
        for (int nf = 0; nf < 4; nf++) {
            int r0 = row0 + mbase + mf * 16 + g;
            int c = col0 + nbase + nf * 8 + 2 * q;
            if (c >= N) continue;
#pragma unroll
            for (int rr = 0; rr < 2; rr++) {
                int r = r0 + rr * 8;
                float x0 = acc[mf][nf][rr * 2 + 0];
                float x1 = acc[mf][nf][rr * 2 + 1];
                if (epi == 0) {
                    *(float2*)((float*)jb.O + (size_t)r * N + c) = make_float2(x0, x1);
                } else if (epi == 6) {
                    __half2 hv = __floats2half2_rn(x0, x1);
                    *(__half2*)((__half*)jb.O + (size_t)r * N + c) = hv;
                } else if (epi == 1) {
                    __half2 hv = __floats2half2_rn(tanhf(x0), tanhf(x1));
                    *(__half2*)((__half*)jb.O + (size_t)r * N + c) = hv;
                } else if (epi == 2) {
                    __half2 hv = __floats2half2_rn(sigmoidf_(x0), sigmoidf_(x1));
                    *(__half2*)((__half*)jb.O + (size_t)r * N + c) = hv;
                } else if (epi == 3) {
                    float y0 = sigmoidf_(x0 + __ldg(jb.bias + c));
                    float y1 = sigmoidf_(x1 + __ldg(jb.bias + c + 1));
                    *(float2*)((float*)jb.O + (size_t)r * N + c) = make_float2(y0, y1);
                } else if (epi == 4) {
                    float y0 = DECAY_SCALE * sigmoidf_(x0 + __ldg(jb.bias + c));
                    float y1 = DECAY_SCALE * sigmoidf_(x1 + __ldg(jb.bias + c + 1));
                    *(float2*)((float*)jb.O + (size_t)r * N + c) = make_float2(y0, y1);
                } else { // 5
                    size_t i0 = (size_t)r * N + c;
                    float s0 = sigmoidf_(x0 + __ldg(jb.bias + c));
                    float s1 = sigmoidf_(x1 + __ldg(jb.bias + c + 1));
                    float a0 = jb.p1[i0], b0 = jb.p2[i0];
                    float a1 = jb.p1[i0 + 1], b1 = jb.p2[i0 + 1];
                    float y0 = fmaf(s0, b0 - a0, a0);
                    float y1 = fmaf(s1, b1 - a1, a1);
                    *(float2*)((float*)jb.O + i0) = make_float2(y0, y1);
                }
            }
        }
    }
}

// ---------------- prep: kk-normalize, k-final, scan precomputes ------------
__global__ void prep_kernel(const float* __restrict__ k_k, const float* __restrict__ k_a) {
    int gid = blockIdx.x * (blockDim.x >> 5) + (threadIdx.x >> 5);
    int lane = threadIdx.x & 31;
    if (gid >= BTn * Hn) return;
    int bt = gid >> 4, h = gid & 15;
    size_t base = (size_t)bt * Cn + h * Dn;
    int c0 = h * Dn + lane, c1 = c0 + 32;

    float k0a = g_k0[base + lane], k0b = g_k0[base + lane + 32];
    float q0 = k0a * k_k[c0], q1 = k0b * k_k[c1];
    float s = q0 * q0 + q1 * q1;
#pragma unroll
    for (int off = 16; off > 0; off >>= 1) s += __shfl_xor_sync(0xffffffffu, s, off);
    float inv = 1.f / fmaxf(sqrtf(s), 1e-12f);
    float kk0 = q0 * inv, kk1 = q1 * inv;

    float a0 = g_a[base + lane], a1 = g_a[base + lane + 32];
    float kf0 = k0a * (1.f + (a0 - 1.f) * k_a[c0]);
    float kf1 = k0b * (1.f + (a1 - 1.f) * k_a[c1]);
    float m0 = expf(g_w[base + lane]), m1 = expf(g_w[base + lane + 32]);
    float r0 = g_r[base + lane], r1 = g_r[base + lane + 32];
    float b0 = kk0 * a0, b1 = kk1 * a1;

    g_m[base + lane] = m0;          g_m[base + lane + 32] = m1;
    g_ad[base + lane] = -kk0 * m0;  g_ad[base + lane + 32] = -kk1 * m1;
    g_rd[base + lane] = r0 * m0;    g_rd[base + lane + 32] = r1 * m1;
    g_bb[base + lane] = b0;         g_bb[base + lane + 32] = b1;
    g_kf[base + lane] = kf0;        g_kf[base + lane + 32] = kf1;

    float rb = r0 * b0 + r1 * b1;
    float rk = r0 * kf0 + r1 * kf1;
#pragma unroll
    for (int off = 16; off > 0; off >>= 1) {
        rb += __shfl_xor_sync(0xffffffffu, rb, off);
        rk += __shfl_xor_sync(0xffffffffu, rk, off);
    }
    if (lane == 0) { g_rb[gid] = rb; g_rk[gid] = rk; }
}

// ---------------- sequential WKV7 scan, column-parallel ---------------------
__global__ __launch_bounds__(128, 1) void scan_kernel(float* __restrict__ out) {
    const int bx = blockIdx.x;
    const int bh = bx >> 1, half = bx & 1;
    const int b = bh >> 4, h = bh & 15;
    const int tid = threadIdx.x;
    const int wid = tid >> 5, lane = tid & 31;
    const int c = lane & 7, dq = lane >> 3;
    const int e = half * 32 + wid * 8 + c;
    const int d0 = dq * 16;
    const int bT0 = b * Tn;

    __shared__ float sb[2][5][SS][64];
    __shared__ float sv[2][SS][32];
    __shared__ float sc[2][2][SS];

    float2 S[8];
#pragma unroll
    for (int i = 0; i < 8; i++) S[i] = make_float2(0.f, 0.f);

    const float* aps[5] = { g_m, g_ad, g_rd, g_bb, g_kf };

    auto stage = [&](int ss, int bufI) {
#pragma unroll
        for (int j = tid; j < 704; j += 128) {
            if (j < 640) {
                int arr = j >> 7, rem = j & 127, s = rem >> 4, f4 = rem & 15;
                const float* src = aps[arr] + ((size_t)(bT0 + ss * SS + s)) * Cn + h * Dn + f4 * 4;
                cpasync16(&sb[bufI][arr][s][f4 * 4], src, 16);
            } else {
                int jj = j - 640;
                int s = jj >> 3, f4 = jj & 7;
                const float* src = g_v + ((size_t)(bT0 + ss * SS + s)) * Cn + h * Dn + half * 32 + f4 * 4;
                cpasync16(&sv[bufI][s][f4 * 4], src, 16);
            }
        }
        if (tid < 16) {
            int arr = tid >> 3, s = tid & 7;
            const float* src = (arr ? g_rk : g_rb) + (size_t)(bT0 + ss * SS + s) * Hn + h;
            cpasync4(&sc[bufI][arr][s], src);
        }
        cpcommit();
    };

    stage(0, 0);

    for (int ss = 0; ss < Tn / SS; ss++) {
        const int cur = ss & 1;
        cpwait0();
        __syncthreads();
        if (ss + 1 < Tn / SS) stage(ss + 1, cur ^ 1);

#pragma unroll 2
        for (int s = 0; s < SS; s++) {
            float4 ad4[4], rd4[4];
#pragma unroll
            for (int i = 0; i < 4; i++) {
                ad4[i] = *(const float4*)&sb[cur][1][s][d0 + i * 4];
                rd4[i] = *(const float4*)&sb[cur][2][s][d0 + i * 4];
            }
            const float2* ad2 = (const float2*)ad4;
            const float2* rd2 = (const float2*)rd4;

            float2 tA = make_float2(0.f, 0.f), tB = make_float2(0.f, 0.f);
            float2 rA = make_float2(0.f, 0.f), rB = make_float2(0.f, 0.f);
#pragma unroll
            for (int i = 0; i < 8; i += 2) {
                tA = ffma2(ad2[i], S[i], tA);
                tB = ffma2(ad2[i + 1], S[i + 1], tB);
                rA = ffma2(rd2[i], S[i], rA);
                rB = ffma2(rd2[i + 1], S[i + 1], rB);
            }
            float ta = (tA.x + tB.x) + (tA.y + tB.y);
            float ro = (rA.x + rB.x) + (rA.y + rB.y);

            float4 m4[4], b4[4], k4[4];
#pragma unroll
            for (int i = 0; i < 4; i++) {
                m4[i] = *(const float4*)&sb[cur][0][s][d0 + i * 4];
                b4[i] = *(const float4*)&sb[cur][3][s][d0 + i * 4];
                k4[i] = *(const float4*)&sb[cur][4][s][d0 + i * 4];
            }
            float v = sv[cur][s][wid * 8 + c];
            float rb = sc[cur][0][s], rk = sc[cur][1][s];

            ta += __shfl_xor_sync(0xffffffffu, ta, 8);
            ro += __shfl_xor_sync(0xffffffffu, ro, 8);
            ta += __shfl_xor_sync(0xffffffffu, ta, 16);
            ro += __shfl_xor_sync(0xffffffffu, ro, 16);

            const float2* m2 = (const float2*)m4;
            const float2* b2 = (const float2*)b4;
            const float2* k2 = (const float2*)k4;
            float2 ta2 = make_float2(ta, ta), v2 = make_float2(v, v);
#pragma unroll
            for (int i = 0; i < 8; i++) {
                float2 t1 = fmul2(k2[i], v2);
                t1 = ffma2(b2[i], ta2, t1);
                S[i] = ffma2(m2[i], S[i], t1);
            }
            if (dq == 0) {
                out[((size_t)(bT0 + ss * SS + s)) * Cn + h * Dn + e] =
                    fmaf(rb, ta, fmaf(rk, v, ro));
            }
        }
    }
}

// ---------------- GroupNorm + corr + gate (writes fp16 g_y) ----------------
__global__ void post_kernel(const float* __restrict__ r_k, const float* __restrict__ gn_w,
                            const float* __restrict__ gn_b) {
    int gid = blockIdx.x * (blockDim.x >> 5) + (threadIdx.x >> 5);
    int lane = threadIdx.x & 31;
    if (gid >= Bn * Tn * Hn) return;
    size_t base = (size_t)(gid >> 4) * Cn + (gid & 15) * Dn;
    int h = gid & 15;
    int c0 = h * Dn + lane, c1 = c0 + 32;
    float o0 = g_osc[base + lane], o1 = g_osc[base + lane + 32];
    float s1 = o0 + o1;
    float s2 = o0 * o0 + o1 * o1;
    float rr0 = g_r[base + lane], rr1 = g_r[base + lane + 32];
    float kk0 = g_kf[base + lane], kk1 = g_kf[base + lane + 32];
    float dp = rr0 * kk0 * r_k[c0] + rr1 * kk1 * r_k[c1];
#pragma unroll
    for (int off = 16; off > 0; off >>= 1) {
        s1 += __shfl_xor_sync(0xffffffffu, s1, off);
        s2 += __shfl_xor_sync(0xffffffffu, s2, off);
        dp += __shfl_xor_sync(0xffffffffu, dp, off);
    }
    float mu = s1 * (1.f / 64.f);
    float var = s2 * (1.f / 64.f) - mu * mu;
    float inv = 1.f / sqrtf(var + GN_EPS);
    float v0 = g_v[base + lane], v1 = g_v[base + lane + 32];
    float y0 = ((o0 - mu) * inv * gn_w[c0] + gn_b[c0] + dp * v0) * g_g[base + lane];
    float y1 = ((o1 - mu) * inv * gn_w[c1] + gn_b[c1] + dp * v1) * g_g[base + lane + 32];
    g_y[base + lane] = __float2half_rn(y0);
    g_y[base + lane + 32] = __float2half_rn(y1);
}

// ---------------- launch ----------------------------------------------------
extern "C" void kernel_launch(void* const* d_in, const int* in_sizes, int n_in,
                              void* d_out, int out_size) {
    const float* hs     = (const float*)d_in[0];
    const float* vfirst = (const float*)d_in[1];
    const float* xmix   = (const float*)d_in[2];
    const float* k_k    = (const float*)d_in[3];
    const float* k_a    = (const float*)d_in[4];
    const float* r_k    = (const float*)d_in[5];
    const float* W_r    = (const float*)d_in[6];
    const float* W_k    = (const float*)d_in[7];
    const float* W_v    = (const float*)d_in[8];
    const float* W_o    = (const float*)d_in[9];
    const float* w_A    = (const float*)d_in[10];
    const float* w_B    = (const float*)d_in[11];
    const float* w_b    = (const float*)d_in[12];
    const float* a_A    = (const float*)d_in[13];
    const float* a_B    = (const float*)d_in[14];
    const float* a_b    = (const float*)d_in[15];
    const float* v_A    = (const float*)d_in[16];
    const float* v_B    = (const float*)d_in[17];
    const float* v_b    = (const float*)d_in[18];
    const float* g_Ain  = (const float*)d_in[19];
    const float* g_Bin  = (const float*)d_in[20];
    const float* gn_w   = (const float*)d_in[21];
    const float* gn_b   = (const float*)d_in[22];
    float* outp = (float*)d_out;

    __half *p_xr, *p_xw, *p_xk, *p_xv, *p_xa, *p_xg, *p_y;
    __half *p_tmpW, *p_tmpA, *p_tmpV, *p_tmpG, *p_wts;
    float *p_r, *p_k0, *p_v, *p_w, *p_a, *p_g, *p_osc;
    cudaGetSymbolAddress((void**)&p_xr, g_xr);
    cudaGetSymbolAddress((void**)&p_xw, g_xw);
    cudaGetSymbolAddress((void**)&p_xk, g_xk);
    cudaGetSymbolAddress((void**)&p_xv, g_xv);
    cudaGetSymbolAddress((void**)&p_xa, g_xa);
    cudaGetSymbolAddress((void**)&p_xg, g_xg);
    cudaGetSymbolAddress((void**)&p_r, g_r);
    cudaGetSymbolAddress((void**)&p_k0, g_k0);
    cudaGetSymbolAddress((void**)&p_v, g_v);
    cudaGetSymbolAddress((void**)&p_w, g_w);
    cudaGetSymbolAddress((void**)&p_a, g_a);
    cudaGetSymbolAddress((void**)&p_g, g_g);
    cudaGetSymbolAddress((void**)&p_osc, g_osc);
    cudaGetSymbolAddress((void**)&p_y, g_y);
    cudaGetSymbolAddress((void**)&p_tmpW, g_tmpW);
    cudaGetSymbolAddress((void**)&p_tmpA, g_tmpA);
    cudaGetSymbolAddress((void**)&p_tmpV, g_tmpV);
    cudaGetSymbolAddress((void**)&p_tmpG, g_tmpG);
    cudaGetSymbolAddress((void**)&p_wts, g_wts);

    const int SMEM = (2 * 128 * LDPh + 2 * BNt * LDPh) * 2;   // 30720
    cudaFuncSetAttribute(gemmTC, cudaFuncAttributeMaxDynamicSharedMemorySize, SMEM);

    // 1. mix + weight fp16 conversion
    {
        int total4 = (NTOK + WTS_TOTAL) / 4;
        mixcvt_kernel<<<(total4 + 255) / 256, 256>>>(hs, xmix, W_r, W_k, W_v, W_o,
                                                     w_A, a_A, v_A, g_Ain,
                                                     w_B, a_B, v_B, g_Bin);
    }

    // 2. merged r/k/v + LoRA stage 1 (z=7)
    {
        Jobs J;
        J.j[0] = { p_xr, p_wts + OFF_Wr, p_r,    nullptr, nullptr, nullptr, 0, Cn,   Cn };
        J.j[1] = { p_xk, p_wts + OFF_Wk, p_k0,   nullptr, nullptr, nullptr, 0, Cn,   Cn };
        J.j[2] = { p_xv, p_wts + OFF_Wv, p_v,    nullptr, nullptr, nullptr, 0, Cn,   Cn };
        J.j[3] = { p_xw, p_wts + OFF_wA, p_tmpW, nullptr, nullptr, nullptr, 1, W_LR, Cn };
        J.j[4] = { p_xa, p_wts + OFF_aA, p_tmpA, nullptr, nullptr, nullptr, 6, A_LR, Cn };
        J.j[5] = { p_xv, p_wts + OFF_vA, p_tmpV, nullptr, nullptr, nullptr, 6, V_LR, Cn };
        J.j[6] = { p_xg, p_wts + OFF_gA, p_tmpG, nullptr, nullptr, nullptr, 2, G_LR, Cn };
        gemmTC<<<dim3(16, 16, 7), 256, SMEM>>>(J);
    }
    // 3. LoRA stage 2 for w,a,v,g (z=4)
    {
        Jobs J;
        J.j[0] = { p_tmpW, p_wts + OFF_wB, p_w, w_b, nullptr, nullptr, 4, Cn, W_LR };
        J.j[1] = { p_tmpA, p_wts + OFF_aB, p_a, a_b, nullptr, nullptr, 3, Cn, A_LR };
        J.j[2] = { p_tmpV, p_wts + OFF_vB, p_v, v_b, p_v, vfirst, 5, Cn, V_LR };
        J.j[3] = { p_tmpG, p_wts + OFF_gB, p_g, nullptr, nullptr, nullptr, 0, Cn, G_LR };
        gemmTC<<<dim3(16, 16, 4), 256, SMEM>>>(J);
    }
    // 4. prep (kk norm, k final, scan precomputes)
    prep_kernel<<<(BTn * Hn + 7) / 8, 256>>>(k_k, k_a);

    // 5. sequential scan
    scan_kernel<<<Bn * Hn * 2, 128>>>(p_osc);

    // 6. groupnorm + corr + gate -> fp16 y
    post_kernel<<<(Bn * Tn * Hn + 7) / 8, 256>>>(r_k, gn_w, gn_b);

    // 7. output projection (A = fp16 y)
    {
        Jobs J;
        J.j[0] = { p_y, p_wts + OFF_Wo, outp, nullptr, nullptr, nullptr, 0, Cn, Cn };
        J.j[1] = J.j[0]; J.j[2] = J.j[0]; J.j[3] = J.j[0];
        J.j[4] = J.j[0]; J.j[5] = J.j[0]; J.j[6] = J.j[0];
        gemmTC<<<dim3(16, 16, 1), 256, SMEM>>>(J);
    }
}

// round 15
// speedup vs baseline: 1.1748x; 1.0149x over previous
#include <cuda_runtime.h>
#include <cuda_fp16.h>
#include <math.h>
#include <stdint.h>

// Problem dims
#define Bn 2
#define Tn 1024
#define Cn 1024
#define Hn 16
#define Dn 64
#define BTn (Bn * Tn)
#define NTOK (Bn * Tn * Cn)
#define W_LR 64
#define A_LR 64
#define V_LR 64
#define G_LR 160
#define DECAY_SCALE (-0.6065306597126334f)
#define GN_EPS (64.0f * 1e-5f)
#define SS 8

// fp16 weight scratch offsets (in elements)
#define OFF_Wr 0
#define OFF_Wk 1048576
#define OFF_Wv 2097152
#define OFF_Wo 3145728
#define OFF_wA 4194304
#define OFF_aA 4259840
#define OFF_vA 4325376
#define OFF_gA 4390912
#define OFF_wB 4554752
#define OFF_aB 4620288
#define OFF_vB 4685824
#define OFF_gB 4751360
#define WTS_TOTAL 4915200

// ---------------- scratch (__device__ globals) -----------------------------
__device__ __align__(16) __half g_xr[NTOK], g_xw[NTOK], g_xk[NTOK], g_xv[NTOK], g_xa[NTOK], g_xg[NTOK];
__device__ float g_r[NTOK], g_k0[NTOK], g_v[NTOK], g_w[NTOK], g_a[NTOK], g_g[NTOK];
__device__ float g_kf[NTOK];
__device__ float g_m[NTOK], g_ad[NTOK], g_rd[NTOK], g_bb[NTOK];
__device__ float g_rb[BTn * Hn], g_rk[BTn * Hn];
__device__ float g_osc[NTOK];
__device__ __align__(16) __half g_y[NTOK];
__device__ __align__(16) __half g_tmpW[BTn * W_LR], g_tmpA[BTn * A_LR], g_tmpV[BTn * V_LR], g_tmpG[BTn * G_LR];
__device__ __align__(16) __half g_wts[WTS_TOTAL];

// ---------------- helpers --------------------------------------------------
__device__ __forceinline__ float sigmoidf_(float x) { return 1.f / (1.f + expf(-x)); }

__device__ __forceinline__ void cpasync16(void* smem, const void* gptr, int srcbytes) {
    uint32_t s = (uint32_t)__cvta_generic_to_shared(smem);
    asm volatile("cp.async.ca.shared.global [%0], [%1], 16, %2;" :: "r"(s), "l"(gptr), "r"(srcbytes));
}
__device__ __forceinline__ void cpasync4(void* smem, const void* gptr) {
    uint32_t s = (uint32_t)__cvta_generic_to_shared(smem);
    asm volatile("cp.async.ca.shared.global [%0], [%1], 4;" :: "r"(s), "l"(gptr));
}
__device__ __forceinline__ void cpcommit() { asm volatile("cp.async.commit_group;"); }
__device__ __forceinline__ void cpwait1() { asm volatile("cp.async.wait_group 1;"); }
__device__ __forceinline__ void cpwait0() { asm volatile("cp.async.wait_group 0;"); }

__device__ __forceinline__ float2 ffma2(float2 a, float2 b, float2 c) {
    unsigned long long ua = *(unsigned long long*)&a;
    unsigned long long ub = *(unsigned long long*)&b;
    unsigned long long uc = *(unsigned long long*)&c;
    unsigned long long ud;
    asm("fma.rn.f32x2 %0, %1, %2, %3;" : "=l"(ud) : "l"(ua), "l"(ub), "l"(uc));
    return *(float2*)&ud;
}
__device__ __forceinline__ float2 fmul2(float2 a, float2 b) {
    unsigned long long ua = *(unsigned long long*)&a;
    unsigned long long ub = *(unsigned long long*)&b;
    unsigned long long ud;
    asm("mul.rn.f32x2 %0, %1, %2;" : "=l"(ud) : "l"(ua), "l"(ub));
    return *(float2*)&ud;
}

__device__ __forceinline__ void mma_f16(float* d, const uint32_t* a, const uint32_t* b) {
    asm volatile(
        "mma.sync.aligned.m16n8k16.row.col.f32.f16.f16.f32 "
        "{%0,%1,%2,%3}, {%4,%5,%6,%7}, {%8,%9}, {%0,%1,%2,%3};"
        : "+f"(d[0]), "+f"(d[1]), "+f"(d[2]), "+f"(d[3])
        : "r"(a[0]), "r"(a[1]), "r"(a[2]), "r"(a[3]), "r"(b[0]), "r"(b[1]));
}

__device__ __forceinline__ void ldsm_x4(uint32_t* r, uint32_t saddr) {
    asm volatile("ldmatrix.sync.aligned.m8n8.x4.shared.b16 {%0,%1,%2,%3}, [%4];"
        : "=r"(r[0]), "=r"(r[1]), "=r"(r[2]), "=r"(r[3]) : "r"(saddr));
}
__device__ __forceinline__ void ldsm_x2(uint32_t* r, uint32_t saddr) {
    asm volatile("ldmatrix.sync.aligned.m8n8.x2.shared.b16 {%0,%1}, [%2];"
        : "=r"(r[0]), "=r"(r[1]) : "r"(saddr));
}

// ---------------- mix + weight fp16 conversion, vectorized -----------------
__device__ __forceinline__ uint2 mix4h(float4 h, float4 d, const float* mxp) {
    float4 mx = *(const float4*)mxp;
    __half2 lo = __floats2half2_rn(fmaf(d.x, mx.x, h.x), fmaf(d.y, mx.y, h.y));
    __half2 hi = __floats2half2_rn(fmaf(d.z, mx.z, h.z), fmaf(d.w, mx.w, h.w));
    uint2 r;
    r.x = *(uint32_t*)&lo; r.y = *(uint32_t*)&hi;
    return r;
}

__global__ void mixcvt_kernel(const float* __restrict__ hs, const float* __restrict__ xmix,
                              const float* __restrict__ Wr, const float* __restrict__ Wk,
                              const float* __restrict__ Wv, const float* __restrict__ Wo,
                              const float* __restrict__ wA, const float* __restrict__ aA,
                              const float* __restrict__ vA, const float* __restrict__ gA,
                              const float* __restrict__ wB, const float* __restrict__ aB,
                              const float* __restrict__ vB, const float* __restrict__ gB) {
    int i4 = blockIdx.x * blockDim.x + threadIdx.x;
    const int NTOK4 = NTOK / 4;
    if (i4 < NTOK4) {
        int base = i4 * 4;
        int c = base & (Cn - 1);
        int t = (base / Cn) & (Tn - 1);
        float4 h = *(const float4*)(hs + base);
        float4 p = (t == 0) ? make_float4(0.f, 0.f, 0.f, 0.f)
                            : *(const float4*)(hs + base - Cn);
        float4 d = make_float4(p.x - h.x, p.y - h.y, p.z - h.z, p.w - h.w);
        *(uint2*)(g_xr + base) = mix4h(h, d, xmix + 0 * Cn + c);
        *(uint2*)(g_xw + base) = mix4h(h, d, xmix + 1 * Cn + c);
        *(uint2*)(g_xk + base) = mix4h(h, d, xmix + 2 * Cn + c);
        *(uint2*)(g_xv + base) = mix4h(h, d, xmix + 3 * Cn + c);
        *(uint2*)(g_xa + base) = mix4h(h, d, xmix + 4 * Cn + c);
        *(uint2*)(g_xg + base) = mix4h(h, d, xmix + 5 * Cn + c);
    } else {
        int j = (i4 - NTOK4) * 4;
        if (j >= WTS_TOTAL) return;
        const float* src;
        if (j < OFF_Wk)      src = Wr + (j - OFF_Wr);
        else if (j < OFF_Wv) src = Wk + (j - OFF_Wk);
        else if (j < OFF_Wo) src = Wv + (j - OFF_Wv);
        else if (j < OFF_wA) src = Wo + (j - OFF_Wo);
        else if (j < OFF_aA) src = wA + (j - OFF_wA);
        else if (j < OFF_vA) src = aA + (j - OFF_aA);
        else if (j < OFF_gA) src = vA + (j - OFF_vA);
        else if (j < OFF_wB) src = gA + (j - OFF_gA);
        else if (j < OFF_aB) src = wB + (j - OFF_wB);
        else if (j < OFF_vB) src = aB + (j - OFF_aB);
        else if (j < OFF_gB) src = vB + (j - OFF_vB);
        else                 src = gB + (j - OFF_gB);
        float4 v = *(const float4*)src;
        __half2 lo = __floats2half2_rn(v.x, v.y);
        __half2 hi = __floats2half2_rn(v.z, v.w);
        uint2 r; r.x = *(uint32_t*)&lo; r.y = *(uint32_t*)&hi;
        *(uint2*)(g_wts + j) = r;
    }
}

// ---------------- tensor-core fp16 GEMM, BM=128 BN=64 BK=32, ldmatrix ------
struct Job {
    const __half* A; const __half* W; void* O;
    const float* bias; const float* p1; const float* p2;
    int epi; int N; int K;
};
struct Jobs { Job j[7]; };

#define LDPh 40
#define BNt 64
#define MF 2

__global__ __launch_bounds__(256, 3) void gemmTC(Jobs jobs) {
    extern __shared__ __half hsm[];
    __half* As = hsm;                       // [2][128][LDPh]
    __half* Bs = hsm + 2 * 128 * LDPh;      // [2][64][LDPh]

    Job jb = jobs.j[blockIdx.z];
    const int N = jb.N, K = jb.K;
    const int row0 = blockIdx.y * 128;
    const int col0 = blockIdx.x * BNt;
    if (col0 >= N) return;
    const int tid = threadIdx.x;
    const int wid = tid >> 5, lane = tid & 31;
    const int wm = wid & 3, wn = wid >> 2;
    const int mbase = wm * 32, nbase = wn * 32;
    const int g = lane >> 2, q = lane & 3;

    const int arow = tid >> 1;
    const int ah0 = (tid & 1) * 16;

    auto stageTiles = [&](int kt, int b) {
        const __half* Ap = jb.A + (size_t)(row0 + arow) * K + kt * 32 + ah0;
        __half* Ad = &As[(b * 128 + arow) * LDPh + ah0];
        cpasync16(Ad + 0, Ap + 0, 16);
        cpasync16(Ad + 8, Ap + 8, 16);
        int brow = tid >> 2, bh0 = (tid & 3) * 8;
        int bn0 = col0 + brow;
        const __half* Bp = jb.W + (size_t)bn0 * K + kt * 32 + bh0;
        cpasync16(&Bs[(b * BNt + brow) * LDPh + bh0], Bp, (bn0 < N) ? 16 : 0);
        cpcommit();
    };

    float acc[MF][4][4];
#pragma unroll
    for (int i = 0; i < MF; i++)
#pragma unroll
        for (int j2 = 0; j2 < 4; j2++)
#pragma unroll
            for (int k2 = 0; k2 < 4; k2++) acc[i][j2][k2] = 0.f;

    const int nk = K >> 5;

    const int l7 = lane & 7, lb3 = (lane >> 3) & 1, lb4 = (lane >> 4) & 1;
    const uint32_t sAbase = (uint32_t)__cvta_generic_to_shared(As);
    const uint32_t sBbase = (uint32_t)__cvta_generic_to_shared(Bs);
    const uint32_t aOffW = (uint32_t)((mbase + l7 + lb3 * 8) * 20 + lb4 * 4);
    const uint32_t bOffW = (uint32_t)((nbase + l7) * 20 + lb3 * 4);

    stageTiles(0, 0);

    for (int kt = 0; kt < nk; kt++) {
        const int buf = kt & 1;
        if (kt + 1 < nk) {
            stageTiles(kt + 1, buf ^ 1);
            cpwait1();
        } else {
            cpwait0();
        }
        __syncthreads();

        const uint32_t aB0 = sAbase + (buf * 128 * 20 + aOffW) * 4;
        const uint32_t bB0 = sBbase + (buf * BNt * 20 + bOffW) * 4;
#pragma unroll
        for (int kw = 0; kw < 16; kw += 8) {
            uint32_t af[MF][4], bf[4][2];
#pragma unroll
            for (int mf = 0; mf < MF; mf++)
                ldsm_x4(af[mf], aB0 + (mf * 16 * 20 + kw) * 4);
#pragma unroll
            for (int nf = 0; nf < 4; nf++)
                ldsm_x2(bf[nf], bB0 + (nf * 8 * 20 + kw) * 4);
#pragma unroll
            for (int mf = 0; mf < MF; mf++)
#pragma unroll
                for (int nf = 0; nf < 4; nf++) mma_f16(acc[mf][nf], af[mf], bf[nf]);
        }
        __syncthreads();
    }

    const int epi = jb.epi;
#pragma unroll
    for (int mf = 0; mf < MF; mf++) {
#pragma unroll
        for (int nf = 0; nf < 4; nf++) {
            int r0 = row0 + mbase + mf * 16 + g;
            int c = col0 + nbase + nf * 8 + 2 * q;
            if (c >= N) continue;
#pragma unroll
            for (int rr = 0; rr < 2; rr++) {
                int r = r0 + rr * 8;
                float x0 = acc[mf][nf][rr * 2 + 0];
                float x1 = acc[mf][nf][rr * 2 + 1];
                if (epi == 0) {
                    *(float2*)((float*)jb.O + (size_t)r * N + c) = make_float2(x0, x1);
                } else if (epi == 6) {
                    __half2 hv = __floats2half2_rn(x0, x1);
                    *(__half2*)((__half*)jb.O + (size_t)r * N + c) = hv;
                } else if (epi == 1) {
                    __half2 hv = __floats2half2_rn(tanhf(x0), tanhf(x1));
                    *(__half2*)((__half*)jb.O + (size_t)r * N + c) = hv;
                } else if (epi == 2) {
                    __half2 hv = __floats2half2_rn(sigmoidf_(x0), sigmoidf_(x1));
                    *(__half2*)((__half*)jb.O + (size_t)r * N + c) = hv;
                } else if (epi == 3) {
                    float y0 = sigmoidf_(x0 + __ldg(jb.bias + c));
                    float y1 = sigmoidf_(x1 + __ldg(jb.bias + c + 1));
                    *(float2*)((float*)jb.O + (size_t)r * N + c) = make_float2(y0, y1);
                } else if (epi == 4) {
                    float y0 = DECAY_SCALE * sigmoidf_(x0 + __ldg(jb.bias + c));
                    float y1 = DECAY_SCALE * sigmoidf_(x1 + __ldg(jb.bias + c + 1));
                    *(float2*)((float*)jb.O + (size_t)r * N + c) = make_float2(y0, y1);
                } else { // 5
                    size_t i0 = (size_t)r * N + c;
                    float s0 = sigmoidf_(x0 + __ldg(jb.bias + c));
                    float s1 = sigmoidf_(x1 + __ldg(jb.bias + c + 1));
                    float a0 = jb.p1[i0], b0 = jb.p2[i0];
                    float a1 = jb.p1[i0 + 1], b1 = jb.p2[i0 + 1];
                    float y0 = fmaf(s0, b0 - a0, a0);
                    float y1 = fmaf(s1, b1 - a1, a1);
                    *(float2*)((float*)jb.O + i0) = make_float2(y0, y1);
                }
            }
        }
    }
}

// ---------------- prep: kk-normalize, k-final, scan precomputes ------------
__global__ void prep_kernel(const float* __restrict__ k_k, const float* __restrict__ k_a) {
    int gid = blockIdx.x * (blockDim.x >> 5) + (threadIdx.x >> 5);
    int lane = threadIdx.x & 31;
    if (gid >= BTn * Hn) return;
    int bt = gid >> 4, h = gid & 15;
    size_t base = (size_t)bt * Cn + h * Dn;
    int c0 = h * Dn + lane, c1 = c0 + 32;

    float k0a = g_k0[base + lane], k0b = g_k0[base + lane + 32];
    float q0 = k0a * k_k[c0], q1 = k0b * k_k[c1];
    float s = q0 * q0 + q1 * q1;
#pragma unroll
    for (int off = 16; off > 0; off >>= 1) s += __shfl_xor_sync(0xffffffffu, s, off);
    float inv = 1.f / fmaxf(sqrtf(s), 1e-12f);
    float kk0 = q0 * inv, kk1 = q1 * inv;

    float a0 = g_a[base + lane], a1 = g_a[base + lane + 32];
    float kf0 = k0a * (1.f + (a0 - 1.f) * k_a[c0]);
    float kf1 = k0b * (1.f + (a1 - 1.f) * k_a[c1]);
    float m0 = expf(g_w[base + lane]), m1 = expf(g_w[base + lane + 32]);
    float r0 = g_r[base + lane], r1 = g_r[base + lane + 32];
    float b0 = kk0 * a0, b1 = kk1 * a1;

    g_m[base + lane] = m0;          g_m[base + lane + 32] = m1;
    g_ad[base + lane] = -kk0 * m0;  g_ad[base + lane + 32] = -kk1 * m1;
    g_rd[base + lane] = r0 * m0;    g_rd[base + lane + 32] = r1 * m1;
    g_bb[base + lane] = b0;         g_bb[base + lane + 32] = b1;
    g_kf[base + lane] = kf0;        g_kf[base + lane + 32] = kf1;

    float rb = r0 * b0 + r1 * b1;
    float rk = r0 * kf0 + r1 * kf1;
#pragma unroll
    for (int off = 16; off > 0; off >>= 1) {
        rb += __shfl_xor_sync(0xffffffffu, rb, off);
        rk += __shfl_xor_sync(0xffffffffu, rk, off);
    }
    if (lane == 0) { g_rb[gid] = rb; g_rk[gid] = rk; }
}

// ---------------- sequential WKV7 scan, software-pipelined dot operands ----
__global__ __launch_bounds__(128, 1) void scan_kernel(float* __restrict__ out) {
    const int bx = blockIdx.x;
    const int bh = bx >> 1, half = bx & 1;
    const int b = bh >> 4, h = bh & 15;
    const int tid = threadIdx.x;
    const int wid = tid >> 5, lane = tid & 31;
    const int c = lane & 7, dq = lane >> 3;
    const int e = half * 32 + wid * 8 + c;
    const int d0 = dq * 16;
    const int bT0 = b * Tn;

    __shared__ float sb[2][5][SS][64];
    __shared__ float sv[2][SS][32];
    __shared__ float sc[2][2][SS];

    float2 S[8];
#pragma unroll
    for (int i = 0; i < 8; i++) S[i] = make_float2(0.f, 0.f);

    const float* aps[5] = { g_m, g_ad, g_rd, g_bb, g_kf };

    auto stage = [&](int ss, int bufI) {
#pragma unroll
        for (int j = tid; j < 704; j += 128) {
            if (j < 640) {
                int arr = j >> 7, rem = j & 127, s = rem >> 4, f4 = rem & 15;
                const float* src = aps[arr] + ((size_t)(bT0 + ss * SS + s)) * Cn + h * Dn + f4 * 4;
                cpasync16(&sb[bufI][arr][s][f4 * 4], src, 16);
            } else {
                int jj = j - 640;
                int s = jj >> 3, f4 = jj & 7;
                const float* src = g_v + ((size_t)(bT0 + ss * SS + s)) * Cn + h * Dn + half * 32 + f4 * 4;
                cpasync16(&sv[bufI][s][f4 * 4], src, 16);
            }
        }
        if (tid < 16) {
            int arr = tid >> 3, s = tid & 7;
            const float* src = (arr ? g_rk : g_rb) + (size_t)(bT0 + ss * SS + s) * Hn + h;
            cpasync4(&sc[bufI][arr][s], src);
        }
        cpcommit();
    };

    stage(0, 0);

    for (int ss = 0; ss < Tn / SS; ss++) {
        const int cur = ss & 1;
        cpwait0();
        __syncthreads();
        if (ss + 1 < Tn / SS) stage(ss + 1, cur ^ 1);

        // preload dot operands for step 0 of this stage
        float4 adC[4], rdC[4];
#pragma unroll
        for (int i = 0; i < 4; i++) {
            adC[i] = *(const float4*)&sb[cur][1][0][d0 + i * 4];
            rdC[i] = *(const float4*)&sb[cur][2][0][d0 + i * 4];
        }

#pragma unroll
        for (int s = 0; s < SS; s++) {
            const float2* ad2 = (const float2*)adC;
            const float2* rd2 = (const float2*)rdC;

            float2 tA = make_float2(0.f, 0.f), tB = make_float2(0.f, 0.f);
            float2 rA = make_float2(0.f, 0.f), rB = make_float2(0.f, 0.f);
#pragma unroll
            for (int i = 0; i < 8; i += 2) {
                tA = ffma2(ad2[i], S[i], tA);
                tB = ffma2(ad2[i + 1], S[i + 1], tB);
                rA = ffma2(rd2[i], S[i], rA);
                rB = ffma2(rd2[i + 1], S[i + 1], rB);
            }
            float ta = (tA.x + tB.x) + (tA.y + tB.y);
            float ro = (rA.x + rB.x) + (rA.y + rB.y);

            // issue next step's dot-operand loads + this step's tail operands
            // before the shfl pair so their latency overlaps the shuffles
            float4 adN[4], rdN[4];
            if (s + 1 < SS) {
#pragma unroll
                for (int i = 0; i < 4; i++) {
                    adN[i] = *(const float4*)&sb[cur][1][s + 1][d0 + i * 4];
                    rdN[i] = *(const float4*)&sb[cur][2][s + 1][d0 + i * 4];
                }
            }
            float4 m4[4], b4[4], k4[4];
#pragma unroll
            for (int i = 0; i < 4; i++) {
                m4[i] = *(const float4*)&sb[cur][0][s][d0 + i * 4];
                b4[i] = *(const float4*)&sb[cur][3][s][d0 + i * 4];
                k4[i] = *(const float4*)&sb[cur][4][s][d0 + i * 4];
            }
            float v = sv[cur][s][wid * 8 + c];
            float rb = sc[cur][0][s], rk = sc[cur][1][s];

            ta += __shfl_xor_sync(0xffffffffu, ta, 8);
            ro += __shfl_xor_sync(0xffffffffu, ro, 8);
            ta += __shfl_xor_sync(0xffffffffu, ta, 16);
            ro += __shfl_xor_sync(0xffffffffu, ro, 16);

            const float2* m2 = (const float2*)m4;
            const float2* b2 = (const float2*)b4;
            const float2* k2 = (const float2*)k4;
            float2 ta2 = make_float2(ta, ta), v2 = make_float2(v, v);
#pragma unroll
            for (int i = 0; i < 8; i++) {
                float2 t1 = fmul2(k2[i], v2);
                t1 = ffma2(b2[i], ta2, t1);
                S[i] = ffma2(m2[i], S[i], t1);
            }
            if (dq == 0) {
                out[((size_t)(bT0 + ss * SS + s)) * Cn + h * Dn + e] =
                    fmaf(rb, ta, fmaf(rk, v, ro));
            }
            if (s + 1 < SS) {
#pragma unroll
                for (int i = 0; i < 4; i++) { adC[i] = adN[i]; rdC[i] = rdN[i]; }
            }
        }
    }
}

// ---------------- GroupNorm + corr + gate (writes fp16 g_y) ----------------
__global__ void post_kernel(const float* __restrict__ r_k, const float* __restrict__ gn_w,
                            const float* __restrict__ gn_b) {
    int gid = blockIdx.x * (blockDim.x >> 5) + (threadIdx.x >> 5);
    int lane = threadIdx.x & 31;
    if (gid >= Bn * Tn * Hn) return;
    size_t base = (size_t)(gid >> 4) * Cn + (gid & 15) * Dn;
    int h = gid & 15;
    int c0 = h * Dn + lane, c1 = c0 + 32;
    float o0 = g_osc[base + lane], o1 = g_osc[base + lane + 32];
    float s1 = o0 + o1;
    float s2 = o0 * o0 + o1 * o1;
    float rr0 = g_r[base + lane], rr1 = g_r[base + lane + 32];
    float kk0 = g_kf[base + lane], kk1 = g_kf[base + lane + 32];
    float dp = rr0 * kk0 * r_k[c0] + rr1 * kk1 * r_k[c1];
#pragma unroll
    for (int off = 16; off > 0; off >>= 1) {
        s1 += __shfl_xor_sync(0xffffffffu, s1, off);
        s2 += __shfl_xor_sync(0xffffffffu, s2, off);
        dp += __shfl_xor_sync(0xffffffffu, dp, off);
    }
    float mu = s1 * (1.f / 64.f);
    float var = s2 * (1.f / 64.f) - mu * mu;
    float inv = 1.f / sqrtf(var + GN_EPS);
    float v0 = g_v[base + lane], v1 = g_v[base + lane + 32];
    float y0 = ((o0 - mu) * inv * gn_w[c0] + gn_b[c0] + dp * v0) * g_g[base + lane];
    float y1 = ((o1 - mu) * inv * gn_w[c1] + gn_b[c1] + dp * v1) * g_g[base + lane + 32];
    g_y[base + lane] = __float2half_rn(y0);
    g_y[base + lane + 32] = __float2half_rn(y1);
}

// ---------------- launch ----------------------------------------------------
extern "C" void kernel_launch(void* const* d_in, const int* in_sizes, int n_in,
                              void* d_out, int out_size) {
    const float* hs     = (const float*)d_in[0];
    const float* vfirst = (const float*)d_in[1];
    const float* xmix   = (const float*)d_in[2];
    const float* k_k    = (const float*)d_in[3];
    const float* k_a    = (const float*)d_in[4];
    const float* r_k    = (const float*)d_in[5];
    const float* W_r    = (const float*)d_in[6];
    const float* W_k    = (const float*)d_in[7];
    const float* W_v    = (const float*)d_in[8];
    const float* W_o    = (const float*)d_in[9];
    const float* w_A    = (const float*)d_in[10];
    const float* w_B    = (const float*)d_in[11];
    const float* w_b    = (const float*)d_in[12];
    const float* a_A    = (const float*)d_in[13];
    const float* a_B    = (const float*)d_in[14];
    const float* a_b    = (const float*)d_in[15];
    const float* v_A    = (const float*)d_in[16];
    const float* v_B    = (const float*)d_in[17];
    const float* v_b    = (const float*)d_in[18];
    const float* g_Ain  = (const float*)d_in[19];
    const float* g_Bin  = (const float*)d_in[20];
    const float* gn_w   = (const float*)d_in[21];
    const float* gn_b   = (const float*)d_in[22];
    float* outp = (float*)d_out;

    __half *p_xr, *p_xw, *p_xk, *p_xv, *p_xa, *p_xg, *p_y;
    __half *p_tmpW, *p_tmpA, *p_tmpV, *p_tmpG, *p_wts;
    float *p_r, *p_k0, *p_v, *p_w, *p_a, *p_g, *p_osc;
    cudaGetSymbolAddress((void**)&p_xr, g_xr);
    cudaGetSymbolAddress((void**)&p_xw, g_xw);
    cudaGetSymbolAddress((void**)&p_xk, g_xk);
    cudaGetSymbolAddress((void**)&p_xv, g_xv);
    cudaGetSymbolAddress((void**)&p_xa, g_xa);
    cudaGetSymbolAddress((void**)&p_xg, g_xg);
    cudaGetSymbolAddress((void**)&p_r, g_r);
    cudaGetSymbolAddress((void**)&p_k0, g_k0);
    cudaGetSymbolAddress((void**)&p_v, g_v);
    cudaGetSymbolAddress((void**)&p_w, g_w);
    cudaGetSymbolAddress((void**)&p_a, g_a);
    cudaGetSymbolAddress((void**)&p_g, g_g);
    cudaGetSymbolAddress((void**)&p_osc, g_osc);
    cudaGetSymbolAddress((void**)&p_y, g_y);
    cudaGetSymbolAddress((void**)&p_tmpW, g_tmpW);
    cudaGetSymbolAddress((void**)&p_tmpA, g_tmpA);
    cudaGetSymbolAddress((void**)&p_tmpV, g_tmpV);
    cudaGetSymbolAddress((void**)&p_tmpG, g_tmpG);
    cudaGetSymbolAddress((void**)&p_wts, g_wts);

    const int SMEM = (2 * 128 * LDPh + 2 * BNt * LDPh) * 2;   // 30720
    cudaFuncSetAttribute(gemmTC, cudaFuncAttributeMaxDynamicSharedMemorySize, SMEM);

    // 1. mix + weight fp16 conversion
    {
        int total4 = (NTOK + WTS_TOTAL) / 4;
        mixcvt_kernel<<<(total4 + 255) / 256, 256>>>(hs, xmix, W_r, W_k, W_v, W_o,
                                                     w_A, a_A, v_A, g_Ain,
                                                     w_B, a_B, v_B, g_Bin);
    }

    // 2. merged r/k/v + LoRA stage 1 (z=7)
    {
        Jobs J;
        J.j[0] = { p_xr, p_wts + OFF_Wr, p_r,    nullptr, nullptr, nullptr, 0, Cn,   Cn };
        J.j[1] = { p_xk, p_wts + OFF_Wk, p_k0,   nullptr, nullptr, nullptr, 0, Cn,   Cn };
        J.j[2] = { p_xv, p_wts + OFF_Wv, p_v,    nullptr, nullptr, nullptr, 0, Cn,   Cn };
        J.j[3] = { p_xw, p_wts + OFF_wA, p_tmpW, nullptr, nullptr, nullptr, 1, W_LR, Cn };
        J.j[4] = { p_xa, p_wts + OFF_aA, p_tmpA, nullptr, nullptr, nullptr, 6, A_LR, Cn };
        J.j[5] = { p_xv, p_wts + OFF_vA, p_tmpV, nullptr, nullptr, nullptr, 6, V_LR, Cn };
        J.j[6] = { p_xg, p_wts + OFF_gA, p_tmpG, nullptr, nullptr, nullptr, 2, G_LR, Cn };
        gemmTC<<<dim3(16, 16, 7), 256, SMEM>>>(J);
    }
    // 3. LoRA stage 2 for w,a,v,g (z=4)
    {
        Jobs J;
        J.j[0] = { p_tmpW, p_wts + OFF_wB, p_w, w_b, nullptr, nullptr, 4, Cn, W_LR };
        J.j[1] = { p_tmpA, p_wts + OFF_aB, p_a, a_b, nullptr, nullptr, 3, Cn, A_LR };
        J.j[2] = { p_tmpV, p_wts + OFF_vB, p_v, v_b, p_v, vfirst, 5, Cn, V_LR };
        J.j[3] = { p_tmpG, p_wts + OFF_gB, p_g, nullptr, nullptr, nullptr, 0, Cn, G_LR };
        gemmTC<<<dim3(16, 16, 4), 256, SMEM>>>(J);
    }
    // 4. prep (kk norm, k final, scan precomputes)
    prep_kernel<<<(BTn * Hn + 7) / 8, 256>>>(k_k, k_a);

    // 5. sequential scan
    scan_kernel<<<Bn * Hn * 2, 128>>>(p_osc);

    // 6. groupnorm + corr + gate -> fp16 y
    post_kernel<<<(Bn * Tn * Hn + 7) / 8, 256>>>(r_k, gn_w, gn_b);

    // 7. output projection (A = fp16 y)
    {
        Jobs J;
        J.j[0] = { p_y, p_wts + OFF_Wo, outp, nullptr, nullptr, nullptr, 0, Cn, Cn };
        J.j[1] = J.j[0]; J.j[2] = J.j[0]; J.j[3] = J.j[0];
        J.j[4] = J.j[0]; J.j[5] = J.j[0]; J.j[6] = J.j[0];
        gemmTC<<<dim3(16, 16, 1), 256, SMEM>>>(J);
    }
}

// round 16
// speedup vs baseline: 1.2616x; 1.0739x over previous
#include <cuda_runtime.h>
#include <cuda_fp16.h>
#include <math.h>
#include <stdint.h>

// Problem dims
#define Bn 2
#define Tn 1024
#define Cn 1024
#define Hn 16
#define Dn 64
#define BTn (Bn * Tn)
#define NTOK (Bn * Tn * Cn)
#define W_LR 64
#define A_LR 64
#define V_LR 64
#define G_LR 160
#define DECAY_SCALE (-0.6065306597126334f)
#define GN_EPS (64.0f * 1e-5f)
#define SS 8

// fp16 weight scratch offsets (in elements)
#define OFF_Wr 0
#define OFF_Wk 1048576
#define OFF_Wv 2097152
#define OFF_Wo 3145728
#define OFF_wA 4194304
#define OFF_aA 4259840
#define OFF_vA 4325376
#define OFF_gA 4390912
#define OFF_wB 4554752
#define OFF_aB 4620288
#define OFF_vB 4685824
#define OFF_gB 4751360
#define WTS_TOTAL 4915200

// ---------------- scratch (__device__ globals) -----------------------------
__device__ __align__(16) __half g_xr[NTOK], g_xw[NTOK], g_xk[NTOK], g_xv[NTOK], g_xa[NTOK], g_xg[NTOK];
__device__ float g_r[NTOK], g_k0[NTOK], g_v[NTOK], g_w[NTOK], g_a[NTOK], g_g[NTOK];
__device__ float g_kf[NTOK];
__device__ float g_m[NTOK], g_ad[NTOK], g_rd[NTOK], g_bb[NTOK];
__device__ float g_rb[BTn * Hn], g_rk[BTn * Hn];
__device__ float g_osc[NTOK];
__device__ __align__(16) __half g_y[NTOK];
__device__ __align__(16) __half g_tmpW[BTn * W_LR], g_tmpA[BTn * A_LR], g_tmpV[BTn * V_LR], g_tmpG[BTn * G_LR];
__device__ __align__(16) __half g_wts[WTS_TOTAL];

// ---------------- helpers --------------------------------------------------
__device__ __forceinline__ float sigmoidf_(float x) { return 1.f / (1.f + expf(-x)); }

__device__ __forceinline__ void cpasync16(void* smem, const void* gptr, int srcbytes) {
    uint32_t s = (uint32_t)__cvta_generic_to_shared(smem);
    asm volatile("cp.async.ca.shared.global [%0], [%1], 16, %2;" :: "r"(s), "l"(gptr), "r"(srcbytes));
}
__device__ __forceinline__ void cpasync4(void* smem, const void* gptr) {
    uint32_t s = (uint32_t)__cvta_generic_to_shared(smem);
    asm volatile("cp.async.ca.shared.global [%0], [%1], 4;" :: "r"(s), "l"(gptr));
}
__device__ __forceinline__ void cpcommit() { asm volatile("cp.async.commit_group;"); }
__device__ __forceinline__ void cpwait1() { asm volatile("cp.async.wait_group 1;"); }
__device__ __forceinline__ void cpwait0() { asm volatile("cp.async.wait_group 0;"); }

__device__ __forceinline__ float2 ffma2(float2 a, float2 b, float2 c) {
    unsigned long long ua = *(unsigned long long*)&a;
    unsigned long long ub = *(unsigned long long*)&b;
    unsigned long long uc = *(unsigned long long*)&c;
    unsigned long long ud;
    asm("fma.rn.f32x2 %0, %1, %2, %3;" : "=l"(ud) : "l"(ua), "l"(ub), "l"(uc));
    return *(float2*)&ud;
}
__device__ __forceinline__ float2 fmul2(float2 a, float2 b) {
    unsigned long long ua = *(unsigned long long*)&a;
    unsigned long long ub = *(unsigned long long*)&b;
    unsigned long long ud;
    asm("mul.rn.f32x2 %0, %1, %2;" : "=l"(ud) : "l"(ua), "l"(ub));
    return *(float2*)&ud;
}

__device__ __forceinline__ void mma_f16(float* d, const uint32_t* a, const uint32_t* b) {
    asm volatile(
        "mma.sync.aligned.m16n8k16.row.col.f32.f16.f16.f32 "
        "{%0,%1,%2,%3}, {%4,%5,%6,%7}, {%8,%9}, {%0,%1,%2,%3};"
        : "+f"(d[0]), "+f"(d[1]), "+f"(d[2]), "+f"(d[3])
        : "r"(a[0]), "r"(a[1]), "r"(a[2]), "r"(a[3]), "r"(b[0]), "r"(b[1]));
}

__device__ __forceinline__ void ldsm_x4(uint32_t* r, uint32_t saddr) {
    asm volatile("ldmatrix.sync.aligned.m8n8.x4.shared.b16 {%0,%1,%2,%3}, [%4];"
        : "=r"(r[0]), "=r"(r[1]), "=r"(r[2]), "=r"(r[3]) : "r"(saddr));
}
__device__ __forceinline__ void ldsm_x2(uint32_t* r, uint32_t saddr) {
    asm volatile("ldmatrix.sync.aligned.m8n8.x2.shared.b16 {%0,%1}, [%2];"
        : "=r"(r[0]), "=r"(r[1]) : "r"(saddr));
}

// ---------------- mix + weight fp16 conversion, vectorized -----------------
__device__ __forceinline__ uint2 mix4h(float4 h, float4 d, const float* mxp) {
    float4 mx = *(const float4*)mxp;
    __half2 lo = __floats2half2_rn(fmaf(d.x, mx.x, h.x), fmaf(d.y, mx.y, h.y));
    __half2 hi = __floats2half2_rn(fmaf(d.z, mx.z, h.z), fmaf(d.w, mx.w, h.w));
    uint2 r;
    r.x = *(uint32_t*)&lo; r.y = *(uint32_t*)&hi;
    return r;
}

__global__ void mixcvt_kernel(const float* __restrict__ hs, const float* __restrict__ xmix,
                              const float* __restrict__ Wr, const float* __restrict__ Wk,
                              const float* __restrict__ Wv, const float* __restrict__ Wo,
                              const float* __restrict__ wA, const float* __restrict__ aA,
                              const float* __restrict__ vA, const float* __restrict__ gA,
                              const float* __restrict__ wB, const float* __restrict__ aB,
                              const float* __restrict__ vB, const float* __restrict__ gB) {
    int i4 = blockIdx.x * blockDim.x + threadIdx.x;
    const int NTOK4 = NTOK / 4;
    if (i4 < NTOK4) {
        int base = i4 * 4;
        int c = base & (Cn - 1);
        int t = (base / Cn) & (Tn - 1);
        float4 h = *(const float4*)(hs + base);
        float4 p = (t == 0) ? make_float4(0.f, 0.f, 0.f, 0.f)
                            : *(const float4*)(hs + base - Cn);
        float4 d = make_float4(p.x - h.x, p.y - h.y, p.z - h.z, p.w - h.w);
        *(uint2*)(g_xr + base) = mix4h(h, d, xmix + 0 * Cn + c);
        *(uint2*)(g_xw + base) = mix4h(h, d, xmix + 1 * Cn + c);
        *(uint2*)(g_xk + base) = mix4h(h, d, xmix + 2 * Cn + c);
        *(uint2*)(g_xv + base) = mix4h(h, d, xmix + 3 * Cn + c);
        *(uint2*)(g_xa + base) = mix4h(h, d, xmix + 4 * Cn + c);
        *(uint2*)(g_xg + base) = mix4h(h, d, xmix + 5 * Cn + c);
    } else {
        int j = (i4 - NTOK4) * 4;
        if (j >= WTS_TOTAL) return;
        const float* src;
        if (j < OFF_Wk)      src = Wr + (j - OFF_Wr);
        else if (j < OFF_Wv) src = Wk + (j - OFF_Wk);
        else if (j < OFF_Wo) src = Wv + (j - OFF_Wv);
        else if (j < OFF_wA) src = Wo + (j - OFF_Wo);
        else if (j < OFF_aA) src = wA + (j - OFF_wA);
        else if (j < OFF_vA) src = aA + (j - OFF_aA);
        else if (j < OFF_gA) src = vA + (j - OFF_vA);
        else if (j < OFF_wB) src = gA + (j - OFF_gA);
        else if (j < OFF_aB) src = wB + (j - OFF_wB);
        else if (j < OFF_vB) src = aB + (j - OFF_aB);
        else if (j < OFF_gB) src = vB + (j - OFF_vB);
        else                 src = gB + (j - OFF_gB);
        float4 v = *(const float4*)src;
        __half2 lo = __floats2half2_rn(v.x, v.y);
        __half2 hi = __floats2half2_rn(v.z, v.w);
        uint2 r; r.x = *(uint32_t*)&lo; r.y = *(uint32_t*)&hi;
        *(uint2*)(g_wts + j) = r;
    }
}

// ---------------- tensor-core fp16 GEMM, BM=128 BN=64 BK=32, ldmatrix ------
struct Job {
    const __half* A; const __half* W; void* O;
    const float* bias; const float* p1; const float* p2;
    int epi; int N; int K;
};
struct Jobs { Job j[7]; };

#define LDPh 40
#define BNt 64
#define MF 2

__global__ __launch_bounds__(256, 3) void gemmTC(Jobs jobs) {
    extern __shared__ __half hsm[];
    __half* As = hsm;                       // [2][128][LDPh]
    __half* Bs = hsm + 2 * 128 * LDPh;      // [2][64][LDPh]

    Job jb = jobs.j[blockIdx.z];
    const int N = jb.N, K = jb.K;
    const int row0 = blockIdx.y * 128;
    const int col0 = blockIdx.x * BNt;
    if (col0 >= N) return;
    const int tid = threadIdx.x;
    const int wid = tid >> 5, lane = tid & 31;
    const int wm = wid & 3, wn = wid >> 2;
    const int mbase = wm * 32, nbase = wn * 32;
    const int g = lane >> 2, q = lane & 3;

    const int arow = tid >> 1;
    const int ah0 = (tid & 1) * 16;

    auto stageTiles = [&](int kt, int b) {
        const __half* Ap = jb.A + (size_t)(row0 + arow) * K + kt * 32 + ah0;
        __half* Ad = &As[(b * 128 + arow) * LDPh + ah0];
        cpasync16(Ad + 0, Ap + 0, 16);
        cpasync16(Ad + 8, Ap + 8, 16);
        int brow = tid >> 2, bh0 = (tid & 3) * 8;
        int bn0 = col0 + brow;
        const __half* Bp = jb.W + (size_t)bn0 * K + kt * 32 + bh0;
        cpasync16(&Bs[(b * BNt + brow) * LDPh + bh0], Bp, (bn0 < N) ? 16 : 0);
        cpcommit();
    };

    float acc[MF][4][4];
#pragma unroll
    for (int i = 0; i < MF; i++)
#pragma unroll
        for (int j2 = 0; j2 < 4; j2++)
#pragma unroll
            for (int k2 = 0; k2 < 4; k2++) acc[i][j2][k2] = 0.f;

    const int nk = K >> 5;

    const int l7 = lane & 7, lb3 = (lane >> 3) & 1, lb4 = (lane >> 4) & 1;
    const uint32_t sAbase = (uint32_t)__cvta_generic_to_shared(As);
    const uint32_t sBbase = (uint32_t)__cvta_generic_to_shared(Bs);
    const uint32_t aOffW = (uint32_t)((mbase + l7 + lb3 * 8) * 20 + lb4 * 4);
    const uint32_t bOffW = (uint32_t)((nbase + l7) * 20 + lb3 * 4);

    stageTiles(0, 0);

    for (int kt = 0; kt < nk; kt++) {
        const int buf = kt & 1;
        if (kt + 1 < nk) {
            stageTiles(kt + 1, buf ^ 1);
            cpwait1();
        } else {
            cpwait0();
        }
        __syncthreads();

        const uint32_t aB0 = sAbase + (buf * 128 * 20 + aOffW) * 4;
        const uint32_t bB0 = sBbase + (buf * BNt * 20 + bOffW) * 4;
#pragma unroll
        for (int kw = 0; kw < 16; kw += 8) {
            uint32_t af[MF][4], bf[4][2];
#pragma unroll
            for (int mf = 0; mf < MF; mf++)
                ldsm_x4(af[mf], aB0 + (mf * 16 * 20 + kw) * 4);
#pragma unroll
            for (int nf = 0; nf < 4; nf++)
                ldsm_x2(bf[nf], bB0 + (nf * 8 * 20 + kw) * 4);
#pragma unroll
            for (int mf = 0; mf < MF; mf++)
#pragma unroll
                for (int nf = 0; nf < 4; nf++) mma_f16(acc[mf][nf], af[mf], bf[nf]);
        }
        __syncthreads();
    }

    const int epi = jb.epi;
#pragma unroll
    for (int mf = 0; mf < MF; mf++) {
#pragma unroll
        for (int nf = 0; nf < 4; nf++) {
            int r0 = row0 + mbase + mf * 16 + g;
            int c = col0 + nbase + nf * 8 + 2 * q;
            if (c >= N) continue;
#pragma unroll
            for (int rr = 0; rr < 2; rr++) {
                int r = r0 + rr * 8;
                float x0 = acc[mf][nf][rr * 2 + 0];
                float x1 = acc[mf][nf][rr * 2 + 1];
                if (epi == 0) {
                    *(float2*)((float*)jb.O + (size_t)r * N + c) = make_float2(x0, x1);
                } else if (epi == 6) {
                    __half2 hv = __floats2half2_rn(x0, x1);
                    *(__half2*)((__half*)jb.O + (size_t)r * N + c) = hv;
                } else if (epi == 1) {
                    __half2 hv = __floats2half2_rn(tanhf(x0), tanhf(x1));
                    *(__half2*)((__half*)jb.O + (size_t)r * N + c) = hv;
                } else if (epi == 2) {
                    __half2 hv = __floats2half2_rn(sigmoidf_(x0), sigmoidf_(x1));
                    *(__half2*)((__half*)jb.O + (size_t)r * N + c) = hv;
                } else if (epi == 3) {
                    float y0 = sigmoidf_(x0 + __ldg(jb.bias + c));
                    float y1 = sigmoidf_(x1 + __ldg(jb.bias + c + 1));
                    *(float2*)((float*)jb.O + (size_t)r * N + c) = make_float2(y0, y1);
                } else if (epi == 4) {
                    float y0 = DECAY_SCALE * sigmoidf_(x0 + __ldg(jb.bias + c));
                    float y1 = DECAY_SCALE * sigmoidf_(x1 + __ldg(jb.bias + c + 1));
                    *(float2*)((float*)jb.O + (size_t)r * N + c) = make_float2(y0, y1);
                } else { // 5
                    size_t i0 = (size_t)r * N + c;
                    float s0 = sigmoidf_(x0 + __ldg(jb.bias + c));
                    float s1 = sigmoidf_(x1 + __ldg(jb.bias + c + 1));
                    float a0 = jb.p1[i0], b0 = jb.p2[i0];
                    float a1 = jb.p1[i0 + 1], b1 = jb.p2[i0 + 1];
                    float y0 = fmaf(s0, b0 - a0, a0);
                    float y1 = fmaf(s1, b1 - a1, a1);
                    *(float2*)((float*)jb.O + i0) = make_float2(y0, y1);
                }
            }
        }
    }
}

// ---------------- prep: kk-normalize, k-final, scan precomputes ------------
__global__ void prep_kernel(const float* __restrict__ k_k, const float* __restrict__ k_a) {
    int gid = blockIdx.x * (blockDim.x >> 5) + (threadIdx.x >> 5);
    int lane = threadIdx.x & 31;
    if (gid >= BTn * Hn) return;
    int bt = gid >> 4, h = gid & 15;
    size_t base = (size_t)bt * Cn + h * Dn;
    int c0 = h * Dn + lane, c1 = c0 + 32;

    float k0a = g_k0[base + lane], k0b = g_k0[base + lane + 32];
    float q0 = k0a * k_k[c0], q1 = k0b * k_k[c1];
    float s = q0 * q0 + q1 * q1;
#pragma unroll
    for (int off = 16; off > 0; off >>= 1) s += __shfl_xor_sync(0xffffffffu, s, off);
    float inv = 1.f / fmaxf(sqrtf(s), 1e-12f);
    float kk0 = q0 * inv, kk1 = q1 * inv;

    float a0 = g_a[base + lane], a1 = g_a[base + lane + 32];
    float kf0 = k0a * (1.f + (a0 - 1.f) * k_a[c0]);
    float kf1 = k0b * (1.f + (a1 - 1.f) * k_a[c1]);
    float m0 = expf(g_w[base + lane]), m1 = expf(g_w[base + lane + 32]);
    float r0 = g_r[base + lane], r1 = g_r[base + lane + 32];
    float b0 = kk0 * a0, b1 = kk1 * a1;

    g_m[base + lane] = m0;          g_m[base + lane + 32] = m1;
    g_ad[base + lane] = -kk0 * m0;  g_ad[base + lane + 32] = -kk1 * m1;
    g_rd[base + lane] = r0 * m0;    g_rd[base + lane + 32] = r1 * m1;
    g_bb[base + lane] = b0;         g_bb[base + lane + 32] = b1;
    g_kf[base + lane] = kf0;        g_kf[base + lane + 32] = kf1;

    float rb = r0 * b0 + r1 * b1;
    float rk = r0 * kf0 + r1 * kf1;
#pragma unroll
    for (int off = 16; off > 0; off >>= 1) {
        rb += __shfl_xor_sync(0xffffffffu, rb, off);
        rk += __shfl_xor_sync(0xffffffffu, rk, off);
    }
    if (lane == 0) { g_rb[gid] = rb; g_rk[gid] = rk; }
}

// ---------------- sequential WKV7 scan: 128 blocks x 64 threads ------------
// block = (b, h, quarter). Warp w covers cols quarter*16 + w*8 + c, dq over d.
__global__ __launch_bounds__(64, 1) void scan_kernel(float* __restrict__ out) {
    const int bx = blockIdx.x;
    const int quarter = bx & 3;
    const int bh = bx >> 2;
    const int b = bh >> 4, h = bh & 15;
    const int tid = threadIdx.x;
    const int wid = tid >> 5, lane = tid & 31;
    const int c = lane & 7, dq = lane >> 3;
    const int e = quarter * 16 + wid * 8 + c;
    const int d0 = dq * 16;
    const int bT0 = b * Tn;

    __shared__ float sb[2][5][SS][64];
    __shared__ float sv[2][SS][16];
    __shared__ float sc[2][2][SS];

    float2 S[8];
#pragma unroll
    for (int i = 0; i < 8; i++) S[i] = make_float2(0.f, 0.f);

    const float* aps[5] = { g_m, g_ad, g_rd, g_bb, g_kf };

    auto stage = [&](int ss, int bufI) {
#pragma unroll
        for (int j = tid; j < 672; j += 64) {
            if (j < 640) {
                int arr = j >> 7, rem = j & 127, s = rem >> 4, f4 = rem & 15;
                const float* src = aps[arr] + ((size_t)(bT0 + ss * SS + s)) * Cn + h * Dn + f4 * 4;
                cpasync16(&sb[bufI][arr][s][f4 * 4], src, 16);
            } else {
                int jj = j - 640;
                int s = jj >> 2, f4 = jj & 3;
                const float* src = g_v + ((size_t)(bT0 + ss * SS + s)) * Cn + h * Dn + quarter * 16 + f4 * 4;
                cpasync16(&sv[bufI][s][f4 * 4], src, 16);
            }
        }
        if (tid < 16) {
            int arr = tid >> 3, s = tid & 7;
            const float* src = (arr ? g_rk : g_rb) + (size_t)(bT0 + ss * SS + s) * Hn + h;
            cpasync4(&sc[bufI][arr][s], src);
        }
        cpcommit();
    };

    stage(0, 0);

    for (int ss = 0; ss < Tn / SS; ss++) {
        const int cur = ss & 1;
        cpwait0();
        __syncthreads();
        if (ss + 1 < Tn / SS) stage(ss + 1, cur ^ 1);

        // preload dot operands for step 0 of this stage
        float4 adC[4], rdC[4];
#pragma unroll
        for (int i = 0; i < 4; i++) {
            adC[i] = *(const float4*)&sb[cur][1][0][d0 + i * 4];
            rdC[i] = *(const float4*)&sb[cur][2][0][d0 + i * 4];
        }

#pragma unroll
        for (int s = 0; s < SS; s++) {
            const float2* ad2 = (const float2*)adC;
            const float2* rd2 = (const float2*)rdC;

            float2 tA = make_float2(0.f, 0.f), tB = make_float2(0.f, 0.f);
            float2 rA = make_float2(0.f, 0.f), rB = make_float2(0.f, 0.f);
#pragma unroll
            for (int i = 0; i < 8; i += 2) {
                tA = ffma2(ad2[i], S[i], tA);
                tB = ffma2(ad2[i + 1], S[i + 1], tB);
                rA = ffma2(rd2[i], S[i], rA);
                rB = ffma2(rd2[i + 1], S[i + 1], rB);
            }
            float ta = (tA.x + tB.x) + (tA.y + tB.y);
            float ro = (rA.x + rB.x) + (rA.y + rB.y);

            float4 adN[4], rdN[4];
            if (s + 1 < SS) {
#pragma unroll
                for (int i = 0; i < 4; i++) {
                    adN[i] = *(const float4*)&sb[cur][1][s + 1][d0 + i * 4];
                    rdN[i] = *(const float4*)&sb[cur][2][s + 1][d0 + i * 4];
                }
            }
            float4 m4[4], b4[4], k4[4];
#pragma unroll
            for (int i = 0; i < 4; i++) {
                m4[i] = *(const float4*)&sb[cur][0][s][d0 + i * 4];
                b4[i] = *(const float4*)&sb[cur][3][s][d0 + i * 4];
                k4[i] = *(const float4*)&sb[cur][4][s][d0 + i * 4];
            }
            float v = sv[cur][s][wid * 8 + c];
            float rb = sc[cur][0][s], rk = sc[cur][1][s];

            ta += __shfl_xor_sync(0xffffffffu, ta, 8);
            ro += __shfl_xor_sync(0xffffffffu, ro, 8);
            ta += __shfl_xor_sync(0xffffffffu, ta, 16);
            ro += __shfl_xor_sync(0xffffffffu, ro, 16);

            const float2* m2 = (const float2*)m4;
            const float2* b2 = (const float2*)b4;
            const float2* k2 = (const float2*)k4;
            float2 ta2 = make_float2(ta, ta), v2 = make_float2(v, v);
#pragma unroll
            for (int i = 0; i < 8; i++) {
                float2 t1 = fmul2(k2[i], v2);
                t1 = ffma2(b2[i], ta2, t1);
                S[i] = ffma2(m2[i], S[i], t1);
            }
            if (dq == 0) {
                out[((size_t)(bT0 + ss * SS + s)) * Cn + h * Dn + e] =
                    fmaf(rb, ta, fmaf(rk, v, ro));
            }
            if (s + 1 < SS) {
#pragma unroll
                for (int i = 0; i < 4; i++) { adC[i] = adN[i]; rdC[i] = rdN[i]; }
            }
        }
    }
}

// ---------------- GroupNorm + corr + gate (writes fp16 g_y) ----------------
__global__ void post_kernel(const float* __restrict__ r_k, const float* __restrict__ gn_w,
                            const float* __restrict__ gn_b) {
    int gid = blockIdx.x * (blockDim.x >> 5) + (threadIdx.x >> 5);
    int lane = threadIdx.x & 31;
    if (gid >= Bn * Tn * Hn) return;
    size_t base = (size_t)(gid >> 4) * Cn + (gid & 15) * Dn;
    int h = gid & 15;
    int c0 = h * Dn + lane, c1 = c0 + 32;
    float o0 = g_osc[base + lane], o1 = g_osc[base + lane + 32];
    float s1 = o0 + o1;
    float s2 = o0 * o0 + o1 * o1;
    float rr0 = g_r[base + lane], rr1 = g_r[base + lane + 32];
    float kk0 = g_kf[base + lane], kk1 = g_kf[base + lane + 32];
    float dp = rr0 * kk0 * r_k[c0] + rr1 * kk1 * r_k[c1];
#pragma unroll
    for (int off = 16; off > 0; off >>= 1) {
        s1 += __shfl_xor_sync(0xffffffffu, s1, off);
        s2 += __shfl_xor_sync(0xffffffffu, s2, off);
        dp += __shfl_xor_sync(0xffffffffu, dp, off);
    }
    float mu = s1 * (1.f / 64.f);
    float var = s2 * (1.f / 64.f) - mu * mu;
    float inv = 1.f / sqrtf(var + GN_EPS);
    float v0 = g_v[base + lane], v1 = g_v[base + lane + 32];
    float y0 = ((o0 - mu) * inv * gn_w[c0] + gn_b[c0] + dp * v0) * g_g[base + lane];
    float y1 = ((o1 - mu) * inv * gn_w[c1] + gn_b[c1] + dp * v1) * g_g[base + lane + 32];
    g_y[base + lane] = __float2half_rn(y0);
    g_y[base + lane + 32] = __float2half_rn(y1);
}

// ---------------- launch ----------------------------------------------------
extern "C" void kernel_launch(void* const* d_in, const int* in_sizes, int n_in,
                              void* d_out, int out_size) {
    const float* hs     = (const float*)d_in[0];
    const float* vfirst = (const float*)d_in[1];
    const float* xmix   = (const float*)d_in[2];
    const float* k_k    = (const float*)d_in[3];
    const float* k_a    = (const float*)d_in[4];
    const float* r_k    = (const float*)d_in[5];
    const float* W_r    = (const float*)d_in[6];
    const float* W_k    = (const float*)d_in[7];
    const float* W_v    = (const float*)d_in[8];
    const float* W_o    = (const float*)d_in[9];
    const float* w_A    = (const float*)d_in[10];
    const float* w_B    = (const float*)d_in[11];
    const float* w_b    = (const float*)d_in[12];
    const float* a_A    = (const float*)d_in[13];
    const float* a_B    = (const float*)d_in[14];
    const float* a_b    = (const float*)d_in[15];
    const float* v_A    = (const float*)d_in[16];
    const float* v_B    = (const float*)d_in[17];
    const float* v_b    = (const float*)d_in[18];
    const float* g_Ain  = (const float*)d_in[19];
    const float* g_Bin  = (const float*)d_in[20];
    const float* gn_w   = (const float*)d_in[21];
    const float* gn_b   = (const float*)d_in[22];
    float* outp = (float*)d_out;

    __half *p_xr, *p_xw, *p_xk, *p_xv, *p_xa, *p_xg, *p_y;
    __half *p_tmpW, *p_tmpA, *p_tmpV, *p_tmpG, *p_wts;
    float *p_r, *p_k0, *p_v, *p_w, *p_a, *p_g, *p_osc;
    cudaGetSymbolAddress((void**)&p_xr, g_xr);
    cudaGetSymbolAddress((void**)&p_xw, g_xw);
    cudaGetSymbolAddress((void**)&p_xk, g_xk);
    cudaGetSymbolAddress((void**)&p_xv, g_xv);
    cudaGetSymbolAddress((void**)&p_xa, g_xa);
    cudaGetSymbolAddress((void**)&p_xg, g_xg);
    cudaGetSymbolAddress((void**)&p_r, g_r);
    cudaGetSymbolAddress((void**)&p_k0, g_k0);
    cudaGetSymbolAddress((void**)&p_v, g_v);
    cudaGetSymbolAddress((void**)&p_w, g_w);
    cudaGetSymbolAddress((void**)&p_a, g_a);
    cudaGetSymbolAddress((void**)&p_g, g_g);
    cudaGetSymbolAddress((void**)&p_osc, g_osc);
    cudaGetSymbolAddress((void**)&p_y, g_y);
    cudaGetSymbolAddress((void**)&p_tmpW, g_tmpW);
    cudaGetSymbolAddress((void**)&p_tmpA, g_tmpA);
    cudaGetSymbolAddress((void**)&p_tmpV, g_tmpV);
    cudaGetSymbolAddress((void**)&p_tmpG, g_tmpG);
    cudaGetSymbolAddress((void**)&p_wts, g_wts);

    const int SMEM = (2 * 128 * LDPh + 2 * BNt * LDPh) * 2;   // 30720
    cudaFuncSetAttribute(gemmTC, cudaFuncAttributeMaxDynamicSharedMemorySize, SMEM);

    // 1. mix + weight fp16 conversion
    {
        int total4 = (NTOK + WTS_TOTAL) / 4;
        mixcvt_kernel<<<(total4 + 255) / 256, 256>>>(hs, xmix, W_r, W_k, W_v, W_o,
                                                     w_A, a_A, v_A, g_Ain,
                                                     w_B, a_B, v_B, g_Bin);
    }

    // 2. merged r/k/v + LoRA stage 1 (z=7)
    {
        Jobs J;
        J.j[0] = { p_xr, p_wts + OFF_Wr, p_r,    nullptr, nullptr, nullptr, 0, Cn,   Cn };
        J.j[1] = { p_xk, p_wts + OFF_Wk, p_k0,   nullptr, nullptr, nullptr, 0, Cn,   Cn };
        J.j[2] = { p_xv, p_wts + OFF_Wv, p_v,    nullptr, nullptr, nullptr, 0, Cn,   Cn };
        J.j[3] = { p_xw, p_wts + OFF_wA, p_tmpW, nullptr, nullptr, nullptr, 1, W_LR, Cn };
        J.j[4] = { p_xa, p_wts + OFF_aA, p_tmpA, nullptr, nullptr, nullptr, 6, A_LR, Cn };
        J.j[5] = { p_xv, p_wts + OFF_vA, p_tmpV, nullptr, nullptr, nullptr, 6, V_LR, Cn };
        J.j[6] = { p_xg, p_wts + OFF_gA, p_tmpG, nullptr, nullptr, nullptr, 2, G_LR, Cn };
        gemmTC<<<dim3(16, 16, 7), 256, SMEM>>>(J);
    }
    // 3. LoRA stage 2 for w,a,v,g (z=4)
    {
        Jobs J;
        J.j[0] = { p_tmpW, p_wts + OFF_wB, p_w, w_b, nullptr, nullptr, 4, Cn, W_LR };
        J.j[1] = { p_tmpA, p_wts + OFF_aB, p_a, a_b, nullptr, nullptr, 3, Cn, A_LR };
        J.j[2] = { p_tmpV, p_wts + OFF_vB, p_v, v_b, p_v, vfirst, 5, Cn, V_LR };
        J.j[3] = { p_tmpG, p_wts + OFF_gB, p_g, nullptr, nullptr, nullptr, 0, Cn, G_LR };
        gemmTC<<<dim3(16, 16, 4), 256, SMEM>>>(J);
    }
    // 4. prep (kk norm, k final, scan precomputes)
    prep_kernel<<<(BTn * Hn + 7) / 8, 256>>>(k_k, k_a);

    // 5. sequential scan — 128 blocks x 64 threads
    scan_kernel<<<Bn * Hn * 4, 64>>>(p_osc);

    // 6. groupnorm + corr + gate -> fp16 y
    post_kernel<<<(Bn * Tn * Hn + 7) / 8, 256>>>(r_k, gn_w, gn_b);

    // 7. output projection (A = fp16 y)
    {
        Jobs J;
        J.j[0] = { p_y, p_wts + OFF_Wo, outp, nullptr, nullptr, nullptr, 0, Cn, Cn };
        J.j[1] = J.j[0]; J.j[2] = J.j[0]; J.j[3] = J.j[0];
        J.j[4] = J.j[0]; J.j[5] = J.j[0]; J.j[6] = J.j[0];
        gemmTC<<<dim3(16, 16, 1), 256, SMEM>>>(J);
    }
}